// round 5
// baseline (speedup 1.0000x reference)
#include <cuda_runtime.h>
#include <math.h>

// ---------------- problem constants ----------------
#define NB    64
#define NCIN  3
#define NHID  128
#define NK    1024

#define S1    31          // conv1 out spatial
#define P1    961         // 31*31
#define S2    30          // conv2 out spatial
#define P2    900         // 30*30
#define NROWS 57600       // 64*900 flat VQ rows
#define NELEMF 7372800.0  // 64*128*900

// ---------------- scratch (device globals; no allocation allowed) ----------
__device__ float  g_z1[NB * NHID * P1];   // encoder conv1 out (relu)
__device__ float  g_z [NB * NHID * P2];   // encoder conv2 out (relu) == flat rows
__device__ float  g_q [NB * NHID * P2];   // quantized (== straight-through value)
__device__ float  g_y [NB * NHID * P1];   // dec1 out (relu)
__device__ float  g_cnorm[NK];
__device__ float  g_znorm[NROWS];
__device__ int    g_counts[NK];
__device__ double g_sse;

// ---------------- init ----------------
__global__ void k_zero() {
    int t = blockIdx.x * blockDim.x + threadIdx.x;
    if (t < NK) g_counts[t] = 0;
    if (t == 0) g_sse = 0.0;
}

// |c|^2 per code: strict sequential mul/add (XLA CPU reduce order)
__global__ void k_cnorm(const float* __restrict__ cb) {
    int c = blockIdx.x * 256 + threadIdx.x;
    if (c < NK) {
        const float* p = cb + c * NHID;
        float s = 0.f;
        for (int d = 0; d < NHID; d++) {
            float m = __fmul_rn(p[d], p[d]);
            s = __fadd_rn(s, m);
        }
        g_cnorm[c] = s;
    }
}

// |z|^2 per flat row (128 consecutive floats of g_z): strict sequential
__global__ void __launch_bounds__(256) k_znorm() {
    __shared__ float s[64 * 129];
    int row0 = blockIdx.x * 64;
    int tid = threadIdx.x;
#pragma unroll
    for (int it = 0; it < 32; it++) {
        int e = tid + 256 * it;
        int r = e >> 7, d = e & 127;
        s[r * 129 + d] = g_z[row0 * NHID + e];
    }
    __syncthreads();
    if (tid < 64) {
        const float* p = s + tid * 129;
        float acc = 0.f;
        for (int d = 0; d < 128; d++) {
            float m = __fmul_rn(p[d], p[d]);
            acc = __fadd_rn(acc, m);
        }
        g_znorm[row0 + tid] = acc;
    }
}

// ---------------- conv1: 3->128, k4, s2, relu ----------------
// Eigen order: single fma chain over (kh, kw, ci), ci innermost
__global__ void __launch_bounds__(256) k_conv1(const float* __restrict__ x,
                                               const float* __restrict__ w,
                                               const float* __restrict__ bias) {
    int b  = blockIdx.z;
    int co = blockIdx.y;
    int pos = blockIdx.x * 256 + threadIdx.x;
    if (pos >= P1) return;
    int oh = pos / S1, ow = pos - oh * S1;
    const float* xb = x + b * (NCIN * 64 * 64);
    const float* wc = w + co * (NCIN * 16);
    float acc = 0.f;
#pragma unroll
    for (int kh = 0; kh < 4; kh++)
#pragma unroll
        for (int kw = 0; kw < 4; kw++)
#pragma unroll
            for (int ci = 0; ci < NCIN; ci++) {
                float xv = xb[ci * 4096 + (oh * 2 + kh) * 64 + (ow * 2 + kw)];
                float wv = __ldg(&wc[ci * 16 + kh * 4 + kw]);
                acc = __fmaf_rn(xv, wv, acc);
            }
    acc = __fadd_rn(acc, bias[co]);
    g_z1[(b * NHID + co) * P1 + pos] = fmaxf(acc, 0.f);
}

// ---------------- conv2: 128->128, k2, s1, relu (implicit GEMM) ----------
// k' = (kh*2+kw)*128 + ci ascending  -> matches Eigen (kh,kw,ci) fma chain
__global__ void __launch_bounds__(256) k_conv2(const float* __restrict__ w,
                                               const float* __restrict__ bias) {
    __shared__ float As[32 * 129];   // [k'][co]
    __shared__ float Bs[32 * 65];    // [k'][pos]
    int b = blockIdx.y;
    int posbase = blockIdx.x * 64;
    int tid = threadIdx.x, tx = tid & 15, ty = tid >> 4;
    const float* zin = g_z1 + b * (NHID * P1);

    float acc[8][4];
#pragma unroll
    for (int i = 0; i < 8; i++)
#pragma unroll
        for (int j = 0; j < 4; j++) acc[i][j] = 0.f;

    for (int kb = 0; kb < 512; kb += 32) {
        __syncthreads();
#pragma unroll
        for (int it = 0; it < 16; it++) {            // W tile 32x128
            int e = tid + 256 * it;
            int kl = e & 31, co = e >> 5;
            int kk = kb + kl;
            int ci = kk & 127, tap = kk >> 7;
            As[kl * 129 + co] = w[co * 512 + ci * 4 + tap];
        }
#pragma unroll
        for (int it = 0; it < 8; it++) {             // Im tile 32x64
            int e = tid + 256 * it;
            int pl = e & 63, kl = e >> 6;
            int kk = kb + kl;
            int ci = kk & 127, tap = kk >> 7;
            int kh = tap >> 1, kw = tap & 1;
            int pos = posbase + pl;
            float v = 0.f;
            if (pos < P2) {
                int oh = pos / S2, ow = pos - oh * S2;
                v = zin[ci * P1 + (oh + kh) * S1 + ow + kw];
            }
            Bs[kl * 65 + pl] = v;
        }
        __syncthreads();
#pragma unroll 4
        for (int kl = 0; kl < 32; kl++) {
            float a[8], bb[4];
            const float* Ap = &As[kl * 129 + ty];
            const float* Bp = &Bs[kl * 65 + tx];
#pragma unroll
            for (int i = 0; i < 8; i++) a[i] = Ap[16 * i];
#pragma unroll
            for (int j = 0; j < 4; j++) bb[j] = Bp[16 * j];
#pragma unroll
            for (int i = 0; i < 8; i++)
#pragma unroll
                for (int j = 0; j < 4; j++)
                    acc[i][j] = __fmaf_rn(a[i], bb[j], acc[i][j]);
        }
    }
#pragma unroll
    for (int i = 0; i < 8; i++) {
        int co = ty + 16 * i;
        float bi = bias[co];
        float* zo = g_z + (b * NHID + co) * P2;
#pragma unroll
        for (int j = 0; j < 4; j++) {
            int pos = posbase + tx + 16 * j;
            if (pos < P2) zo[pos] = fmaxf(__fadd_rn(acc[i][j], bi), 0.f);
        }
    }
}

// ---------------- VQ: fused GEMM + argmin + gather + loss + hist ----------
// d2 = fl(fl(Z - 2*M) + C)  -- replicates reference fp32 quantization grid
extern __shared__ float sm_vq[];
__global__ void __launch_bounds__(256) k_vq(const float* __restrict__ cb) {
    float* As = sm_vq;             // [d(128)][row(64)+pad] stride 65
    float* Bs = sm_vq + 128 * 65;  // [d(128)][code(64)+pad] stride 65
    int row0 = blockIdx.x * 64;
    int tid = threadIdx.x, tx = tid & 15, ty = tid >> 4;
    const float* zrow = g_z + row0 * NHID;

#pragma unroll
    for (int it = 0; it < 32; it++) {      // load 64x128 z tile
        int e = tid + 256 * it;
        int r = e >> 7, d = e & 127;
        As[d * 65 + r] = zrow[e];
    }

    float Zr[4];
#pragma unroll
    for (int i = 0; i < 4; i++) Zr[i] = g_znorm[row0 + ty + 16 * i];

    float minv[4];
    int mini[4];
#pragma unroll
    for (int i = 0; i < 4; i++) { minv[i] = 3.4e38f; mini[i] = 0; }

    for (int c0 = 0; c0 < NK; c0 += 64) {
        __syncthreads();
#pragma unroll
        for (int it = 0; it < 32; it++) {
            int e = tid + 256 * it;
            int c = e >> 7, d = e & 127;
            Bs[d * 65 + c] = cb[(c0 + c) * NHID + d];
        }
        __syncthreads();
        float acc[4][4];
#pragma unroll
        for (int i = 0; i < 4; i++)
#pragma unroll
            for (int j = 0; j < 4; j++) acc[i][j] = 0.f;
#pragma unroll 4
        for (int k = 0; k < 128; k++) {
            float a[4], bv[4];
            const float* Ap = &As[k * 65 + ty];
            const float* Bp = &Bs[k * 65 + tx];
#pragma unroll
            for (int i = 0; i < 4; i++) a[i] = Ap[16 * i];
#pragma unroll
            for (int j = 0; j < 4; j++) bv[j] = Bp[16 * j];
#pragma unroll
            for (int i = 0; i < 4; i++)
#pragma unroll
                for (int j = 0; j < 4; j++)
                    acc[i][j] = __fmaf_rn(a[i], bv[j], acc[i][j]);
        }
#pragma unroll
        for (int j = 0; j < 4; j++) {
            int code = c0 + tx + 16 * j;
            float cn = __ldg(&g_cnorm[code]);
#pragma unroll
            for (int i = 0; i < 4; i++) {
                float t = __fmaf_rn(-2.0f, acc[i][j], Zr[i]);  // fl(Z - 2M), 2M exact
                float s = __fadd_rn(t, cn);                    // fl(.. + C)
                if (s < minv[i]) { minv[i] = s; mini[i] = code; }
            }
        }
    }
    __syncthreads();
    // reduce across the 16 tx threads that share each row (reuse Bs area)
    float* redv = Bs;                    // 64*16 floats
    int*   redi = (int*)(Bs + 1024);     // 64*16 ints
    int*   scode = (int*)(Bs + 2048);    // 64 ints
    float* lred = Bs + 2112;             // 256 floats
#pragma unroll
    for (int i = 0; i < 4; i++) {
        int r = ty + 16 * i;
        redv[r * 16 + tx] = minv[i];
        redi[r * 16 + tx] = mini[i];
    }
    __syncthreads();
    if (tid < 64) {
        float bv = redv[tid * 16];
        int bi = redi[tid * 16];
#pragma unroll
        for (int t = 1; t < 16; t++) {
            float v = redv[tid * 16 + t];
            int ii = redi[tid * 16 + t];
            if (v < bv || (v == bv && ii < bi)) { bv = v; bi = ii; }
        }
        scode[tid] = bi;
        atomicAdd(&g_counts[bi], 1);
    }
    __syncthreads();
    // gather quantized rows + squared-error partial
    float lsum = 0.f;
    float* qout = g_q + row0 * NHID;
#pragma unroll
    for (int it = 0; it < 32; it++) {
        int e = tid + 256 * it;
        int r = e >> 7, d = e & 127;
        int code = scode[r];
        float qv = __ldg(&cb[code * NHID + d]);
        float zv = As[d * 65 + r];
        qout[e] = qv;
        float df = qv - zv;
        lsum += df * df;
    }
    lred[tid] = lsum;
    __syncthreads();
    for (int s = 128; s > 0; s >>= 1) {
        if (tid < s) lred[tid] += lred[tid + s];
        __syncthreads();
    }
    if (tid == 0) atomicAdd(&g_sse, (double)lred[0]);
}

// ---------------- dec1: convT 128->128, k2, s1, relu (implicit GEMM) -----
__global__ void __launch_bounds__(256) k_dec1(const float* __restrict__ w,
                                              const float* __restrict__ bias) {
    __shared__ float As[32 * 129];
    __shared__ float Bs[32 * 65];
    int b = blockIdx.y;
    int posbase = blockIdx.x * 64;
    int tid = threadIdx.x, tx = tid & 15, ty = tid >> 4;
    const float* qin = g_q + b * (NHID * P2);

    float acc[8][4];
#pragma unroll
    for (int i = 0; i < 8; i++)
#pragma unroll
        for (int j = 0; j < 4; j++) acc[i][j] = 0.f;

    for (int kb = 0; kb < 512; kb += 32) {
        __syncthreads();
#pragma unroll
        for (int it = 0; it < 16; it++) {
            int e = tid + 256 * it;
            int kl = e & 31, co = e >> 5;
            int k = kb + kl;
            // dec_w1 layout [ci][co][kh][kw]; k = ci*4 + tap
            As[kl * 129 + co] = w[(k >> 2) * 512 + co * 4 + (k & 3)];
        }
#pragma unroll
        for (int it = 0; it < 8; it++) {
            int e = tid + 256 * it;
            int pl = e & 63, kl = e >> 6;
            int k = kb + kl;
            int ci = k >> 2, kh = (k >> 1) & 1, kw = k & 1;
            int pos = posbase + pl;
            float v = 0.f;
            if (pos < P1) {
                int oh = pos / S1, ow = pos - oh * S1;
                int ih = oh - kh, iw = ow - kw;
                if ((unsigned)ih < (unsigned)S2 && (unsigned)iw < (unsigned)S2)
                    v = qin[ci * P2 + ih * S2 + iw];
            }
            Bs[kl * 65 + pl] = v;
        }
        __syncthreads();
#pragma unroll 4
        for (int kl = 0; kl < 32; kl++) {
            float a[8], bb[4];
            const float* Ap = &As[kl * 129 + ty];
            const float* Bp = &Bs[kl * 65 + tx];
#pragma unroll
            for (int i = 0; i < 8; i++) a[i] = Ap[16 * i];
#pragma unroll
            for (int j = 0; j < 4; j++) bb[j] = Bp[16 * j];
#pragma unroll
            for (int i = 0; i < 8; i++)
#pragma unroll
                for (int j = 0; j < 4; j++)
                    acc[i][j] = __fmaf_rn(a[i], bb[j], acc[i][j]);
        }
    }
#pragma unroll
    for (int i = 0; i < 8; i++) {
        int co = ty + 16 * i;
        float bi = bias[co];
        float* yo = g_y + (b * NHID + co) * P1;
#pragma unroll
        for (int j = 0; j < 4; j++) {
            int pos = posbase + tx + 16 * j;
            if (pos < P1) yo[pos] = fmaxf(acc[i][j] + bi, 0.f);
        }
    }
}

// ---------------- dec2: convT 128->3, k4, s2 -> x_recon ----------------
__global__ void __launch_bounds__(192) k_dec2(const float* __restrict__ w,
                                              const float* __restrict__ bias,
                                              float* __restrict__ out) {
    __shared__ float sy[2 * 128 * 32];   // two input rows, padded width 32
    __shared__ float sw[128 * 3 * 2 * 4];
    int b = blockIdx.y, oh = blockIdx.x;
    int tid = threadIdx.x;
    int p = oh & 1;
    int ih0 = oh >> 1;        // kh = p
    int ih1 = ih0 - 1;        // kh = p + 2
    const float* yb = g_y + b * (NHID * P1);

    for (int e = tid; e < 8192; e += 192) {
        int r = e >> 12;
        int rem = e & 4095;
        int ci = rem >> 5, iw = rem & 31;
        int ih = r ? ih1 : ih0;
        float v = 0.f;
        if (iw < S1 && (unsigned)ih < (unsigned)S1) v = yb[ci * P1 + ih * S1 + iw];
        sy[e] = v;
    }
    for (int e = tid; e < 3072; e += 192) {
        int cico = e >> 3;
        int ci = cico / 3, co = cico - ci * 3;
        int rr = (e >> 2) & 1, kw = e & 3;
        sw[e] = w[ci * 48 + co * 16 + (p + 2 * rr) * 4 + kw];
    }
    __syncthreads();

    int co = tid >> 6;      // 0..2
    int ow = tid & 63;
    int pw = ow & 1;
    int iw0 = ow >> 1;
    int iw1 = iw0 - 1;
    bool ok1 = (iw1 >= 0);
    int iw1c = ok1 ? iw1 : 0;

    float acc = bias[co];
#pragma unroll 4
    for (int ci = 0; ci < NHID; ci++) {
        int swb = (ci * 3 + co) * 8;
        float w00 = sw[swb + pw];
        float w01 = sw[swb + pw + 2];
        float w10 = sw[swb + 4 + pw];
        float w11 = sw[swb + 4 + pw + 2];
        float y00 = sy[ci * 32 + iw0];
        float y01 = ok1 ? sy[ci * 32 + iw1c] : 0.f;
        float y10 = sy[4096 + ci * 32 + iw0];
        float y11 = ok1 ? sy[4096 + ci * 32 + iw1c] : 0.f;
        acc += y00 * w00 + y01 * w01 + y10 * w10 + y11 * w11;
    }
    out[b * (3 * 4096) + co * 4096 + oh * 64 + ow] = acc;
}

// ---------------- finalize: loss + perplexity ----------------
__global__ void k_final(float* __restrict__ out) {
    __shared__ double sd[1024];
    int t = threadIdx.x;
    double pr = (double)g_counts[t] / (double)NROWS;
    sd[t] = pr * log(pr + 1e-10);
    __syncthreads();
    for (int s = 512; s > 0; s >>= 1) {
        if (t < s) sd[t] += sd[t + s];
        __syncthreads();
    }
    if (t == 0) {
        out[786432] = (float)(1.25 * g_sse / NELEMF);  // loss = (1+beta)*mse
        out[786433] = (float)exp(-sd[0]);              // perplexity
    }
}

// ---------------- launch ----------------
extern "C" void kernel_launch(void* const* d_in, const int* in_sizes, int n_in,
                              void* d_out, int out_size) {
    const float* x   = (const float*)d_in[0];
    const float* ew1 = (const float*)d_in[1];
    const float* eb1 = (const float*)d_in[2];
    const float* ew2 = (const float*)d_in[3];
    const float* eb2 = (const float*)d_in[4];
    const float* cb  = (const float*)d_in[5];
    const float* dw1 = (const float*)d_in[6];
    const float* db1 = (const float*)d_in[7];
    const float* dw2 = (const float*)d_in[8];
    const float* db2 = (const float*)d_in[9];
    float* out = (float*)d_out;

    cudaFuncSetAttribute(k_vq, cudaFuncAttributeMaxDynamicSharedMemorySize,
                         2 * 128 * 65 * (int)sizeof(float));

    k_zero<<<1, 1024>>>();
    k_cnorm<<<4, 256>>>(cb);
    k_conv1<<<dim3(4, NHID, NB), 256>>>(x, ew1, eb1);
    k_conv2<<<dim3(15, NB), 256>>>(ew2, eb2);
    k_znorm<<<NROWS / 64, 256>>>();
    k_vq<<<NROWS / 64, 256, 2 * 128 * 65 * (int)sizeof(float)>>>(cb);
    k_dec1<<<dim3(16, NB), 256>>>(dw1, db1);
    k_dec2<<<dim3(64, NB), 192>>>(dw2, db2, out);
    k_final<<<1, 1024>>>(out);
}

// round 6
// speedup vs baseline: 1.2542x; 1.2542x over previous
#include <cuda_runtime.h>
#include <math.h>

// ---------------- problem constants ----------------
#define NB    64
#define NCIN  3
#define NHID  128
#define NK    1024

#define S1    31          // conv1 out spatial
#define P1    961         // 31*31
#define S2    30          // conv2 out spatial
#define P2    900         // 30*30
#define NROWS 57600       // 64*900 flat VQ rows
#define NELEMF 7372800.0  // 64*128*900

// ---------------- scratch (device globals; no allocation allowed) ----------
__device__ float  g_z1[NB * NHID * P1];   // encoder conv1 out (relu)
__device__ float  g_z [NB * NHID * P2];   // encoder conv2 out (relu) == flat rows
__device__ float  g_q [NB * NHID * P2];   // quantized (== straight-through value)
__device__ float  g_y [NB * NHID * P1];   // dec1 out (relu)
__device__ float  g_cnorm[NK];
__device__ float  g_znorm[NROWS];
__device__ int    g_counts[NK];
__device__ double g_sse;

// ---------------- init ----------------
__global__ void k_zero() {
    int t = blockIdx.x * blockDim.x + threadIdx.x;
    if (t < NK) g_counts[t] = 0;
    if (t == 0) g_sse = 0.0;
}

// |c|^2 per code: strict sequential mul/add
__global__ void k_cnorm(const float* __restrict__ cb) {
    int c = blockIdx.x * 256 + threadIdx.x;
    if (c < NK) {
        const float* p = cb + c * NHID;
        float s = 0.f;
        for (int d = 0; d < NHID; d++) {
            float m = __fmul_rn(p[d], p[d]);
            s = __fadd_rn(s, m);
        }
        g_cnorm[c] = s;
    }
}

// |z|^2 per flat row: strict sequential
__global__ void __launch_bounds__(256) k_znorm() {
    __shared__ float s[64 * 129];
    int row0 = blockIdx.x * 64;
    int tid = threadIdx.x;
#pragma unroll
    for (int it = 0; it < 32; it++) {
        int e = tid + 256 * it;
        int r = e >> 7, d = e & 127;
        s[r * 129 + d] = g_z[row0 * NHID + e];
    }
    __syncthreads();
    if (tid < 64) {
        const float* p = s + tid * 129;
        float acc = 0.f;
        for (int d = 0; d < 128; d++) {
            float m = __fmul_rn(p[d], p[d]);
            acc = __fadd_rn(acc, m);
        }
        g_znorm[row0 + tid] = acc;
    }
}

// ---------------- conv1: 3->128, k4, s2, relu (smem GEMM, K=48) ----------
// chain order per output: k = kh*12 + kw*3 + ci ascending == Eigen (kh,kw,ci)
__global__ void __launch_bounds__(256) k_conv1(const float* __restrict__ x,
                                               const float* __restrict__ w,
                                               const float* __restrict__ bias) {
    __shared__ __align__(16) float As[48 * 132];   // [k][co]
    __shared__ __align__(16) float Bs[48 * 68];    // [k][pos]
    int b = blockIdx.y;
    int posbase = blockIdx.x * 64;
    int tid = threadIdx.x, tx = tid & 15, ty = tid >> 4;
    const float* xb = x + b * (NCIN * 64 * 64);

    for (int e = tid; e < 48 * 128; e += 256) {
        int co = e / 48, kl = e - co * 48;
        int kh = kl / 12, r2 = kl - kh * 12;
        int kw = r2 / 3, ci = r2 - kw * 3;
        As[kl * 132 + co] = w[co * 48 + ci * 16 + kh * 4 + kw];
    }
    for (int e = tid; e < 48 * 64; e += 256) {
        int pl = e & 63, kl = e >> 6;
        int kh = kl / 12, r2 = kl - kh * 12;
        int kw = r2 / 3, ci = r2 - kw * 3;
        int pos = posbase + pl;
        float v = 0.f;
        if (pos < P1) {
            int oh = pos / S1, ow = pos - oh * S1;
            v = xb[ci * 4096 + (oh * 2 + kh) * 64 + (ow * 2 + kw)];
        }
        Bs[kl * 68 + pl] = v;
    }
    __syncthreads();

    float acc[8][4];
#pragma unroll
    for (int i = 0; i < 8; i++)
#pragma unroll
        for (int j = 0; j < 4; j++) acc[i][j] = 0.f;

#pragma unroll 8
    for (int kl = 0; kl < 48; kl++) {
        float4 a0 = *(const float4*)(As + kl * 132 + 4 * ty);
        float4 a1 = *(const float4*)(As + kl * 132 + 64 + 4 * ty);
        float4 b0 = *(const float4*)(Bs + kl * 68 + 4 * tx);
        float ar[8] = {a0.x, a0.y, a0.z, a0.w, a1.x, a1.y, a1.z, a1.w};
        float br[4] = {b0.x, b0.y, b0.z, b0.w};
#pragma unroll
        for (int i = 0; i < 8; i++)
#pragma unroll
            for (int j = 0; j < 4; j++)
                acc[i][j] = __fmaf_rn(ar[i], br[j], acc[i][j]);
    }
#pragma unroll
    for (int i = 0; i < 8; i++) {
        int co = (i < 4) ? (4 * ty + i) : (64 + 4 * ty + i - 4);
        float bi = bias[co];
        float* zo = g_z1 + (b * NHID + co) * P1;
#pragma unroll
        for (int j = 0; j < 4; j++) {
            int pos = posbase + 4 * tx + j;
            if (pos < P1) zo[pos] = fmaxf(__fadd_rn(acc[i][j], bi), 0.f);
        }
    }
}

// ---------------- conv2: 128->128, k2, s1, relu (vectorized GEMM) --------
// k' = tap*128 + ci ascending (matches the passing chain order)
__global__ void __launch_bounds__(256) k_conv2(const float* __restrict__ w,
                                               const float* __restrict__ bias) {
    __shared__ __align__(16) float As[32 * 132];   // [k'][co]
    __shared__ __align__(16) float Bs[32 * 68];    // [k'][pos]
    int b = blockIdx.y;
    int posbase = blockIdx.x * 64;
    int tid = threadIdx.x, tx = tid & 15, ty = tid >> 4;
    const float* zin = g_z1 + b * (NHID * P1);

    float acc[8][4];
#pragma unroll
    for (int i = 0; i < 8; i++)
#pragma unroll
        for (int j = 0; j < 4; j++) acc[i][j] = 0.f;

    for (int kb = 0; kb < 512; kb += 32) {
        __syncthreads();
#pragma unroll
        for (int it = 0; it < 16; it++) {            // W tile 32x128
            int e = tid + 256 * it;
            int kl = e & 31, co = e >> 5;
            int kk = kb + kl;
            int ci = kk & 127, tap = kk >> 7;
            As[kl * 132 + co] = w[co * 512 + ci * 4 + tap];
        }
#pragma unroll
        for (int it = 0; it < 8; it++) {             // Im tile 32x64
            int e = tid + 256 * it;
            int pl = e & 63, kl = e >> 6;
            int kk = kb + kl;
            int ci = kk & 127, tap = kk >> 7;
            int kh = tap >> 1, kw = tap & 1;
            int pos = posbase + pl;
            float v = 0.f;
            if (pos < P2) {
                int oh = pos / S2, ow = pos - oh * S2;
                v = zin[ci * P1 + (oh + kh) * S1 + ow + kw];
            }
            Bs[kl * 68 + pl] = v;
        }
        __syncthreads();
#pragma unroll 8
        for (int kl = 0; kl < 32; kl++) {
            float4 a0 = *(const float4*)(As + kl * 132 + 4 * ty);
            float4 a1 = *(const float4*)(As + kl * 132 + 64 + 4 * ty);
            float4 b0 = *(const float4*)(Bs + kl * 68 + 4 * tx);
            float ar[8] = {a0.x, a0.y, a0.z, a0.w, a1.x, a1.y, a1.z, a1.w};
            float br[4] = {b0.x, b0.y, b0.z, b0.w};
#pragma unroll
            for (int i = 0; i < 8; i++)
#pragma unroll
                for (int j = 0; j < 4; j++)
                    acc[i][j] = __fmaf_rn(ar[i], br[j], acc[i][j]);
        }
    }
#pragma unroll
    for (int i = 0; i < 8; i++) {
        int co = (i < 4) ? (4 * ty + i) : (64 + 4 * ty + i - 4);
        float bi = bias[co];
        float* zo = g_z + (b * NHID + co) * P2;
#pragma unroll
        for (int j = 0; j < 4; j++) {
            int pos = posbase + 4 * tx + j;
            if (pos < P2) zo[pos] = fmaxf(__fadd_rn(acc[i][j], bi), 0.f);
        }
    }
}

// ---------------- VQ: fused GEMM + argmin + gather + loss + hist ----------
// d2 = fl(fl(Z - 2*M) + C); per-code chain k=0..127 ascending (unchanged)
extern __shared__ float sm_vq[];
__global__ void __launch_bounds__(256) k_vq(const float* __restrict__ cb) {
    float* As = sm_vq;             // [d(128)][row(64)] stride 68
    float* Bs = sm_vq + 128 * 68;  // [d(128)][code(64)] stride 68
    int row0 = blockIdx.x * 64;
    int tid = threadIdx.x, tx = tid & 15, ty = tid >> 4;
    const float* zrow = g_z + row0 * NHID;

#pragma unroll
    for (int it = 0; it < 32; it++) {      // load 64x128 z tile
        int e = tid + 256 * it;
        int r = e >> 7, d = e & 127;
        As[d * 68 + r] = zrow[e];
    }

    float4 zr4 = *(const float4*)(g_znorm + row0 + 4 * ty);
    float Zr[4] = {zr4.x, zr4.y, zr4.z, zr4.w};

    float minv[4];
    int mini[4];
#pragma unroll
    for (int i = 0; i < 4; i++) { minv[i] = 3.4e38f; mini[i] = 0; }

    for (int c0 = 0; c0 < NK; c0 += 64) {
        __syncthreads();
#pragma unroll
        for (int it = 0; it < 32; it++) {
            int e = tid + 256 * it;
            int c = e >> 7, d = e & 127;
            Bs[d * 68 + c] = cb[(c0 + c) * NHID + d];
        }
        __syncthreads();
        float acc[4][4];
#pragma unroll
        for (int i = 0; i < 4; i++)
#pragma unroll
            for (int j = 0; j < 4; j++) acc[i][j] = 0.f;
#pragma unroll 8
        for (int k = 0; k < 128; k++) {
            float4 a = *(const float4*)(As + k * 68 + 4 * ty);
            float4 bv = *(const float4*)(Bs + k * 68 + 4 * tx);
            float ar[4] = {a.x, a.y, a.z, a.w};
            float br[4] = {bv.x, bv.y, bv.z, bv.w};
#pragma unroll
            for (int i = 0; i < 4; i++)
#pragma unroll
                for (int j = 0; j < 4; j++)
                    acc[i][j] = __fmaf_rn(ar[i], br[j], acc[i][j]);
        }
        float4 cn4 = *(const float4*)(g_cnorm + c0 + 4 * tx);
        float cnr[4] = {cn4.x, cn4.y, cn4.z, cn4.w};
#pragma unroll
        for (int j = 0; j < 4; j++) {
            int code = c0 + 4 * tx + j;
#pragma unroll
            for (int i = 0; i < 4; i++) {
                float t = __fmaf_rn(-2.0f, acc[i][j], Zr[i]);  // fl(Z - 2M)
                float s = __fadd_rn(t, cnr[j]);                // fl(.. + C)
                if (s < minv[i]) { minv[i] = s; mini[i] = code; }
            }
        }
    }
    __syncthreads();
    // reduce across the 16 tx threads that share each row (reuse Bs area)
    float* redv = Bs;                    // 64*16 floats
    int*   redi = (int*)(Bs + 1024);     // 64*16 ints
    int*   scode = (int*)(Bs + 2048);    // 64 ints
    float* lred = Bs + 2112;             // 256 floats
#pragma unroll
    for (int i = 0; i < 4; i++) {
        int r = 4 * ty + i;
        redv[r * 16 + tx] = minv[i];
        redi[r * 16 + tx] = mini[i];
    }
    __syncthreads();
    if (tid < 64) {
        float bv = redv[tid * 16];
        int bi = redi[tid * 16];
#pragma unroll
        for (int t = 1; t < 16; t++) {
            float v = redv[tid * 16 + t];
            int ii = redi[tid * 16 + t];
            if (v < bv || (v == bv && ii < bi)) { bv = v; bi = ii; }
        }
        scode[tid] = bi;
        atomicAdd(&g_counts[bi], 1);
    }
    __syncthreads();
    // gather quantized rows + squared-error partial
    float lsum = 0.f;
    float* qout = g_q + row0 * NHID;
#pragma unroll
    for (int it = 0; it < 32; it++) {
        int e = tid + 256 * it;
        int r = e >> 7, d = e & 127;
        int code = scode[r];
        float qv = __ldg(&cb[code * NHID + d]);
        float zv = As[d * 68 + r];
        qout[e] = qv;
        float df = qv - zv;
        lsum += df * df;
    }
    lred[tid] = lsum;
    __syncthreads();
    for (int s = 128; s > 0; s >>= 1) {
        if (tid < s) lred[tid] += lred[tid + s];
        __syncthreads();
    }
    if (tid == 0) atomicAdd(&g_sse, (double)lred[0]);
}

// ---------------- dec1: convT 128->128, k2, s1, relu (vectorized GEMM) ---
__global__ void __launch_bounds__(256) k_dec1(const float* __restrict__ w,
                                              const float* __restrict__ bias) {
    __shared__ __align__(16) float As[32 * 132];
    __shared__ __align__(16) float Bs[32 * 68];
    int b = blockIdx.y;
    int posbase = blockIdx.x * 64;
    int tid = threadIdx.x, tx = tid & 15, ty = tid >> 4;
    const float* qin = g_q + b * (NHID * P2);

    float acc[8][4];
#pragma unroll
    for (int i = 0; i < 8; i++)
#pragma unroll
        for (int j = 0; j < 4; j++) acc[i][j] = 0.f;

    for (int kb = 0; kb < 512; kb += 32) {
        __syncthreads();
#pragma unroll
        for (int it = 0; it < 16; it++) {
            int e = tid + 256 * it;
            int kl = e & 31, co = e >> 5;
            int k = kb + kl;
            // dec_w1 layout [ci][co][kh][kw]; k = ci*4 + tap
            As[kl * 132 + co] = w[(k >> 2) * 512 + co * 4 + (k & 3)];
        }
#pragma unroll
        for (int it = 0; it < 8; it++) {
            int e = tid + 256 * it;
            int pl = e & 63, kl = e >> 6;
            int k = kb + kl;
            int ci = k >> 2, kh = (k >> 1) & 1, kw = k & 1;
            int pos = posbase + pl;
            float v = 0.f;
            if (pos < P1) {
                int oh = pos / S1, ow = pos - oh * S1;
                int ih = oh - kh, iw = ow - kw;
                if ((unsigned)ih < (unsigned)S2 && (unsigned)iw < (unsigned)S2)
                    v = qin[ci * P2 + ih * S2 + iw];
            }
            Bs[kl * 68 + pl] = v;
        }
        __syncthreads();
#pragma unroll 8
        for (int kl = 0; kl < 32; kl++) {
            float4 a0 = *(const float4*)(As + kl * 132 + 4 * ty);
            float4 a1 = *(const float4*)(As + kl * 132 + 64 + 4 * ty);
            float4 b0 = *(const float4*)(Bs + kl * 68 + 4 * tx);
            float ar[8] = {a0.x, a0.y, a0.z, a0.w, a1.x, a1.y, a1.z, a1.w};
            float br[4] = {b0.x, b0.y, b0.z, b0.w};
#pragma unroll
            for (int i = 0; i < 8; i++)
#pragma unroll
                for (int j = 0; j < 4; j++)
                    acc[i][j] = __fmaf_rn(ar[i], br[j], acc[i][j]);
        }
    }
#pragma unroll
    for (int i = 0; i < 8; i++) {
        int co = (i < 4) ? (4 * ty + i) : (64 + 4 * ty + i - 4);
        float bi = bias[co];
        float* yo = g_y + (b * NHID + co) * P1;
#pragma unroll
        for (int j = 0; j < 4; j++) {
            int pos = posbase + 4 * tx + j;
            if (pos < P1) yo[pos] = fmaxf(acc[i][j] + bi, 0.f);
        }
    }
}

// ---------------- dec2: convT 128->3, k4, s2 -> x_recon ----------------
// one block per (b, oh-pair): both oh parities share the same two y rows
extern __shared__ float sm_d2[];
__global__ void __launch_bounds__(192) k_dec2(const float* __restrict__ w,
                                              const float* __restrict__ bias,
                                              float* __restrict__ out) {
    float* sy = sm_d2;           // [2 rows][128 ci][32 iw] = 8192
    float* sw = sm_d2 + 8192;    // full weights 128*3*16 = 6144
    int b = blockIdx.y, t = blockIdx.x;   // outputs oh = 2t, 2t+1
    int tid = threadIdx.x;
    const float* yb = g_y + b * (NHID * P1);

    for (int e = tid; e < 8192; e += 192) {
        int r = e >> 12;
        int rem = e & 4095;
        int ci = rem >> 5, iw = rem & 31;
        int ih = t - r;
        float v = 0.f;
        if (iw < S1 && (unsigned)ih < (unsigned)S1) v = yb[ci * P1 + ih * S1 + iw];
        sy[e] = v;
    }
    for (int e = tid; e < 6144; e += 192) sw[e] = w[e];
    __syncthreads();

    int co = tid >> 6;      // 0..2
    int ow = tid & 63;
    int pw = ow & 1;
    int iw0 = ow >> 1;
    int iw1 = iw0 - 1;
    bool ok1 = (iw1 >= 0);
    int iw1c = ok1 ? iw1 : 0;

    float accE = 0.f, accO = 0.f;
#pragma unroll 4
    for (int ci = 0; ci < NHID; ci++) {
        float y00 = sy[ci * 32 + iw0];
        float y01 = ok1 ? sy[ci * 32 + iw1c] : 0.f;
        float y10 = sy[4096 + ci * 32 + iw0];
        float y11 = ok1 ? sy[4096 + ci * 32 + iw1c] : 0.f;
        const float* wb = sw + ci * 48 + co * 16;
        accE += y00 * wb[pw]      + y01 * wb[pw + 2]
              + y10 * wb[8 + pw]  + y11 * wb[8 + pw + 2];
        accO += y00 * wb[4 + pw]  + y01 * wb[4 + pw + 2]
              + y10 * wb[12 + pw] + y11 * wb[12 + pw + 2];
    }
    float bi = bias[co];
    int base = b * (3 * 4096) + co * 4096 + (2 * t) * 64 + ow;
    out[base]      = accE + bi;
    out[base + 64] = accO + bi;
}

// ---------------- finalize: loss + perplexity ----------------
__global__ void k_final(float* __restrict__ out) {
    __shared__ double sd[1024];
    int t = threadIdx.x;
    double pr = (double)g_counts[t] / (double)NROWS;
    sd[t] = pr * log(pr + 1e-10);
    __syncthreads();
    for (int s = 512; s > 0; s >>= 1) {
        if (t < s) sd[t] += sd[t + s];
        __syncthreads();
    }
    if (t == 0) {
        out[786432] = (float)(1.25 * g_sse / NELEMF);  // loss = (1+beta)*mse
        out[786433] = (float)exp(-sd[0]);              // perplexity
    }
}

// ---------------- launch ----------------
extern "C" void kernel_launch(void* const* d_in, const int* in_sizes, int n_in,
                              void* d_out, int out_size) {
    const float* x   = (const float*)d_in[0];
    const float* ew1 = (const float*)d_in[1];
    const float* eb1 = (const float*)d_in[2];
    const float* ew2 = (const float*)d_in[3];
    const float* eb2 = (const float*)d_in[4];
    const float* cb  = (const float*)d_in[5];
    const float* dw1 = (const float*)d_in[6];
    const float* db1 = (const float*)d_in[7];
    const float* dw2 = (const float*)d_in[8];
    const float* db2 = (const float*)d_in[9];
    float* out = (float*)d_out;

    cudaFuncSetAttribute(k_vq, cudaFuncAttributeMaxDynamicSharedMemorySize,
                         2 * 128 * 68 * (int)sizeof(float));
    cudaFuncSetAttribute(k_dec2, cudaFuncAttributeMaxDynamicSharedMemorySize,
                         (8192 + 6144) * (int)sizeof(float));

    k_zero<<<1, 1024>>>();
    k_cnorm<<<4, 256>>>(cb);
    k_conv1<<<dim3(16, NB), 256>>>(x, ew1, eb1);
    k_conv2<<<dim3(15, NB), 256>>>(ew2, eb2);
    k_znorm<<<NROWS / 64, 256>>>();
    k_vq<<<NROWS / 64, 256, 2 * 128 * 68 * (int)sizeof(float)>>>(cb);
    k_dec1<<<dim3(16, NB), 256>>>(dw1, db1);
    k_dec2<<<dim3(32, NB), 192, (8192 + 6144) * (int)sizeof(float)>>>(dw2, db2, out);
    k_final<<<1, 1024>>>(out);
}

// round 9
// speedup vs baseline: 1.3896x; 1.1080x over previous
#include <cuda_runtime.h>
#include <cuda_bf16.h>
#include <cstdint>
#include <math.h>

// ---------------- problem constants ----------------
#define NB    64
#define NCIN  3
#define NHID  128
#define NK    1024

#define S1    31          // conv1 out spatial
#define P1    961         // 31*31
#define S2    30          // conv2 out spatial
#define P2    900         // 30*30
#define NROWS 57600       // 64*900 flat VQ rows
#define NELEMF 7372800.0  // 64*128*900

// ---------------- scratch (device globals; no allocation allowed) ----------
__device__ float  g_z1[NB * NHID * P1];   // encoder conv1 out (relu)
__device__ float  g_z [NB * NHID * P2];   // encoder conv2 out (relu) == flat rows
__device__ float  g_q [NB * NHID * P2];   // quantized (== straight-through value)
__device__ float  g_y [NB * NHID * P1];   // dec1 out (relu)
__device__ float  g_cnorm[NK];
__device__ float  g_znorm[NROWS];
__device__ int    g_counts[NK];
__device__ double g_sse;
__device__ __nv_bfloat16 g_whi[NHID * 512];  // dec_w1 split hi, layout [co][k]
__device__ __nv_bfloat16 g_wlo[NHID * 512];  // dec_w1 split lo

// ---------------- init ----------------
__global__ void k_zero() {
    int t = blockIdx.x * blockDim.x + threadIdx.x;
    if (t < NK) g_counts[t] = 0;
    if (t == 0) g_sse = 0.0;
}

// |c|^2 per code: strict sequential mul/add
__global__ void k_cnorm(const float* __restrict__ cb) {
    int c = blockIdx.x * 256 + threadIdx.x;
    if (c < NK) {
        const float* p = cb + c * NHID;
        float s = 0.f;
        for (int d = 0; d < NHID; d++) {
            float m = __fmul_rn(p[d], p[d]);
            s = __fadd_rn(s, m);
        }
        g_cnorm[c] = s;
    }
}

// |z|^2 per flat row: strict sequential
__global__ void __launch_bounds__(256) k_znorm() {
    __shared__ float s[64 * 129];
    int row0 = blockIdx.x * 64;
    int tid = threadIdx.x;
#pragma unroll
    for (int it = 0; it < 32; it++) {
        int e = tid + 256 * it;
        int r = e >> 7, d = e & 127;
        s[r * 129 + d] = g_z[row0 * NHID + e];
    }
    __syncthreads();
    if (tid < 64) {
        const float* p = s + tid * 129;
        float acc = 0.f;
        for (int d = 0; d < 128; d++) {
            float m = __fmul_rn(p[d], p[d]);
            acc = __fadd_rn(acc, m);
        }
        g_znorm[row0 + tid] = acc;
    }
}

// ---------------- dec_w1 bf16 split: Wt[co][k], k = ci*4 + tap ------------
__global__ void k_wsplit(const float* __restrict__ w) {
    int e = blockIdx.x * 256 + threadIdx.x;   // 65536 elems
    int co = e >> 9, k = e & 511;
    int ci = k >> 2, tap = k & 3;
    float v = w[ci * 512 + co * 4 + tap];
    __nv_bfloat16 h = __float2bfloat16(v);
    g_whi[e] = h;
    g_wlo[e] = __float2bfloat16(v - __bfloat162float(h));
}

// ---------------- conv1: 3->128, k4, s2, relu (smem GEMM, K=48) ----------
__global__ void __launch_bounds__(256) k_conv1(const float* __restrict__ x,
                                               const float* __restrict__ w,
                                               const float* __restrict__ bias) {
    __shared__ __align__(16) float As[48 * 132];   // [k][co]
    __shared__ __align__(16) float Bs[48 * 68];    // [k][pos]
    int b = blockIdx.y;
    int posbase = blockIdx.x * 64;
    int tid = threadIdx.x, tx = tid & 15, ty = tid >> 4;
    const float* xb = x + b * (NCIN * 64 * 64);

    for (int e = tid; e < 48 * 128; e += 256) {
        int co = e / 48, kl = e - co * 48;
        int kh = kl / 12, r2 = kl - kh * 12;
        int kw = r2 / 3, ci = r2 - kw * 3;
        As[kl * 132 + co] = w[co * 48 + ci * 16 + kh * 4 + kw];
    }
    for (int e = tid; e < 48 * 64; e += 256) {
        int pl = e & 63, kl = e >> 6;
        int kh = kl / 12, r2 = kl - kh * 12;
        int kw = r2 / 3, ci = r2 - kw * 3;
        int pos = posbase + pl;
        float v = 0.f;
        if (pos < P1) {
            int oh = pos / S1, ow = pos - oh * S1;
            v = xb[ci * 4096 + (oh * 2 + kh) * 64 + (ow * 2 + kw)];
        }
        Bs[kl * 68 + pl] = v;
    }
    __syncthreads();

    float acc[8][4];
#pragma unroll
    for (int i = 0; i < 8; i++)
#pragma unroll
        for (int j = 0; j < 4; j++) acc[i][j] = 0.f;

#pragma unroll 8
    for (int kl = 0; kl < 48; kl++) {
        float4 a0 = *(const float4*)(As + kl * 132 + 4 * ty);
        float4 a1 = *(const float4*)(As + kl * 132 + 64 + 4 * ty);
        float4 b0 = *(const float4*)(Bs + kl * 68 + 4 * tx);
        float ar[8] = {a0.x, a0.y, a0.z, a0.w, a1.x, a1.y, a1.z, a1.w};
        float br[4] = {b0.x, b0.y, b0.z, b0.w};
#pragma unroll
        for (int i = 0; i < 8; i++)
#pragma unroll
            for (int j = 0; j < 4; j++)
                acc[i][j] = __fmaf_rn(ar[i], br[j], acc[i][j]);
    }
#pragma unroll
    for (int i = 0; i < 8; i++) {
        int co = (i < 4) ? (4 * ty + i) : (64 + 4 * ty + i - 4);
        float bi = bias[co];
        float* zo = g_z1 + (b * NHID + co) * P1;
#pragma unroll
        for (int j = 0; j < 4; j++) {
            int pos = posbase + 4 * tx + j;
            if (pos < P1) zo[pos] = fmaxf(__fadd_rn(acc[i][j], bi), 0.f);
        }
    }
}

// ---------------- conv2: 128->128, k2, s1, relu (exact fp32 GEMM) --------
__global__ void __launch_bounds__(256) k_conv2(const float* __restrict__ w,
                                               const float* __restrict__ bias) {
    __shared__ __align__(16) float As[32 * 132];   // [k'][co]
    __shared__ __align__(16) float Bs[32 * 68];    // [k'][pos]
    int b = blockIdx.y;
    int posbase = blockIdx.x * 64;
    int tid = threadIdx.x, tx = tid & 15, ty = tid >> 4;
    const float* zin = g_z1 + b * (NHID * P1);

    float acc[8][4];
#pragma unroll
    for (int i = 0; i < 8; i++)
#pragma unroll
        for (int j = 0; j < 4; j++) acc[i][j] = 0.f;

    for (int kb = 0; kb < 512; kb += 32) {
        __syncthreads();
#pragma unroll
        for (int it = 0; it < 16; it++) {            // W tile 32x128
            int e = tid + 256 * it;
            int kl = e & 31, co = e >> 5;
            int kk = kb + kl;
            int ci = kk & 127, tap = kk >> 7;
            As[kl * 132 + co] = w[co * 512 + ci * 4 + tap];
        }
#pragma unroll
        for (int it = 0; it < 8; it++) {             // Im tile 32x64
            int e = tid + 256 * it;
            int pl = e & 63, kl = e >> 6;
            int kk = kb + kl;
            int ci = kk & 127, tap = kk >> 7;
            int kh = tap >> 1, kw = tap & 1;
            int pos = posbase + pl;
            float v = 0.f;
            if (pos < P2) {
                int oh = pos / S2, ow = pos - oh * S2;
                v = zin[ci * P1 + (oh + kh) * S1 + ow + kw];
            }
            Bs[kl * 68 + pl] = v;
        }
        __syncthreads();
#pragma unroll 8
        for (int kl = 0; kl < 32; kl++) {
            float4 a0 = *(const float4*)(As + kl * 132 + 4 * ty);
            float4 a1 = *(const float4*)(As + kl * 132 + 64 + 4 * ty);
            float4 b0 = *(const float4*)(Bs + kl * 68 + 4 * tx);
            float ar[8] = {a0.x, a0.y, a0.z, a0.w, a1.x, a1.y, a1.z, a1.w};
            float br[4] = {b0.x, b0.y, b0.z, b0.w};
#pragma unroll
            for (int i = 0; i < 8; i++)
#pragma unroll
                for (int j = 0; j < 4; j++)
                    acc[i][j] = __fmaf_rn(ar[i], br[j], acc[i][j]);
        }
    }
#pragma unroll
    for (int i = 0; i < 8; i++) {
        int co = (i < 4) ? (4 * ty + i) : (64 + 4 * ty + i - 4);
        float bi = bias[co];
        float* zo = g_z + (b * NHID + co) * P2;
#pragma unroll
        for (int j = 0; j < 4; j++) {
            int pos = posbase + 4 * tx + j;
            if (pos < P2) zo[pos] = fmaxf(__fadd_rn(acc[i][j], bi), 0.f);
        }
    }
}

// ---------------- VQ: fused GEMM + argmin + gather + loss + hist ----------
extern __shared__ float sm_vq[];
__global__ void __launch_bounds__(256) k_vq(const float* __restrict__ cb) {
    float* As = sm_vq;             // [d(128)][row(64)] stride 68
    float* Bs = sm_vq + 128 * 68;  // [d(128)][code(64)] stride 68
    int row0 = blockIdx.x * 64;
    int tid = threadIdx.x, tx = tid & 15, ty = tid >> 4;
    const float* zrow = g_z + row0 * NHID;

#pragma unroll
    for (int it = 0; it < 32; it++) {      // load 64x128 z tile
        int e = tid + 256 * it;
        int r = e >> 7, d = e & 127;
        As[d * 68 + r] = zrow[e];
    }

    float4 zr4 = *(const float4*)(g_znorm + row0 + 4 * ty);
    float Zr[4] = {zr4.x, zr4.y, zr4.z, zr4.w};

    float minv[4];
    int mini[4];
#pragma unroll
    for (int i = 0; i < 4; i++) { minv[i] = 3.4e38f; mini[i] = 0; }

    for (int c0 = 0; c0 < NK; c0 += 64) {
        __syncthreads();
#pragma unroll
        for (int it = 0; it < 32; it++) {
            int e = tid + 256 * it;
            int c = e >> 7, d = e & 127;
            Bs[d * 68 + c] = cb[(c0 + c) * NHID + d];
        }
        __syncthreads();
        float acc[4][4];
#pragma unroll
        for (int i = 0; i < 4; i++)
#pragma unroll
            for (int j = 0; j < 4; j++) acc[i][j] = 0.f;
#pragma unroll 8
        for (int k = 0; k < 128; k++) {
            float4 a = *(const float4*)(As + k * 68 + 4 * ty);
            float4 bv = *(const float4*)(Bs + k * 68 + 4 * tx);
            float ar[4] = {a.x, a.y, a.z, a.w};
            float br[4] = {bv.x, bv.y, bv.z, bv.w};
#pragma unroll
            for (int i = 0; i < 4; i++)
#pragma unroll
                for (int j = 0; j < 4; j++)
                    acc[i][j] = __fmaf_rn(ar[i], br[j], acc[i][j]);
        }
        float4 cn4 = *(const float4*)(g_cnorm + c0 + 4 * tx);
        float cnr[4] = {cn4.x, cn4.y, cn4.z, cn4.w};
#pragma unroll
        for (int j = 0; j < 4; j++) {
            int code = c0 + 4 * tx + j;
#pragma unroll
            for (int i = 0; i < 4; i++) {
                float t = __fmaf_rn(-2.0f, acc[i][j], Zr[i]);  // fl(Z - 2M)
                float s = __fadd_rn(t, cnr[j]);                // fl(.. + C)
                if (s < minv[i]) { minv[i] = s; mini[i] = code; }
            }
        }
    }
    __syncthreads();
    float* redv = Bs;                    // 64*16 floats
    int*   redi = (int*)(Bs + 1024);     // 64*16 ints
    int*   scode = (int*)(Bs + 2048);    // 64 ints
    float* lred = Bs + 2112;             // 256 floats
#pragma unroll
    for (int i = 0; i < 4; i++) {
        int r = 4 * ty + i;
        redv[r * 16 + tx] = minv[i];
        redi[r * 16 + tx] = mini[i];
    }
    __syncthreads();
    if (tid < 64) {
        float bv = redv[tid * 16];
        int bi = redi[tid * 16];
#pragma unroll
        for (int t = 1; t < 16; t++) {
            float v = redv[tid * 16 + t];
            int ii = redi[tid * 16 + t];
            if (v < bv || (v == bv && ii < bi)) { bv = v; bi = ii; }
        }
        scode[tid] = bi;
        atomicAdd(&g_counts[bi], 1);
    }
    __syncthreads();
    float lsum = 0.f;
    float* qout = g_q + row0 * NHID;
#pragma unroll
    for (int it = 0; it < 32; it++) {
        int e = tid + 256 * it;
        int r = e >> 7, d = e & 127;
        int code = scode[r];
        float qv = __ldg(&cb[code * NHID + d]);
        float zv = As[d * 68 + r];
        qout[e] = qv;
        float df = qv - zv;
        lsum += df * df;
    }
    lred[tid] = lsum;
    __syncthreads();
    for (int s = 128; s > 0; s >>= 1) {
        if (tid < s) lred[tid] += lred[tid + s];
        __syncthreads();
    }
    if (tid == 0) atomicAdd(&g_sse, (double)lred[0]);
}

// ---------------- dec1: convT 128->128, k2, s1, relu -- TENSOR CORES -----
// D[pos][co] = sum_k A[pos][k] * W[k][co], bf16 2-term split (3 mma products)
#define MMA_BF16(d, a0, a1, a2, a3, b0, b1)                                   \
    asm volatile(                                                             \
        "mma.sync.aligned.m16n8k16.row.col.f32.bf16.bf16.f32 "                \
        "{%0,%1,%2,%3}, {%4,%5,%6,%7}, {%8,%9}, {%0,%1,%2,%3};"               \
        : "+f"(d[0]), "+f"(d[1]), "+f"(d[2]), "+f"(d[3])                      \
        : "r"(a0), "r"(a1), "r"(a2), "r"(a3), "r"(b0), "r"(b1))

__global__ void __launch_bounds__(256) k_dec1t(const float* __restrict__ bias) {
    __shared__ __align__(16) __nv_bfloat16 Ah[64 * 40];    // [pos][k] +pad
    __shared__ __align__(16) __nv_bfloat16 Al[64 * 40];
    __shared__ __align__(16) __nv_bfloat16 Wh[128 * 40];   // [co][k] +pad
    __shared__ __align__(16) __nv_bfloat16 Wl[128 * 40];
    int b = blockIdx.y;
    int posbase = blockIdx.x * 64;
    int tid = threadIdx.x;
    int warp = tid >> 5, lane = tid & 31;
    int wm = warp >> 1, wn = warp & 1;          // 4 M-tiles x 2 N-halves
    const float* qin = g_q + b * (NHID * P2);

    float d[8][4];
#pragma unroll
    for (int i = 0; i < 8; i++)
#pragma unroll
        for (int j = 0; j < 4; j++) d[i][j] = 0.f;

    for (int kb = 0; kb < 512; kb += 32) {
        __syncthreads();
        // A tile: 64 pos x 32 k (im2col of q, fp32 -> hi/lo bf16)
#pragma unroll
        for (int it = 0; it < 8; it++) {
            int e = tid + 256 * it;             // 2048 = 64*32
            int pl = e & 63, kl = e >> 6;
            int k = kb + kl;
            int ci = k >> 2, kh = (k >> 1) & 1, kw = k & 1;
            int pos = posbase + pl;
            float v = 0.f;
            if (pos < P1) {
                int oh = pos / S1, ow = pos - oh * S1;
                int ih = oh - kh, iw = ow - kw;
                if ((unsigned)ih < (unsigned)S2 && (unsigned)iw < (unsigned)S2)
                    v = qin[ci * P2 + ih * S2 + iw];
            }
            __nv_bfloat16 h = __float2bfloat16(v);
            Ah[pl * 40 + kl] = h;
            Al[pl * 40 + kl] = __float2bfloat16(v - __bfloat162float(h));
        }
        // W tile: 128 co x 32 k (pre-split)
#pragma unroll
        for (int it = 0; it < 16; it++) {
            int e = tid + 256 * it;             // 4096 = 128*32
            int kl = e & 31, co = e >> 5;
            Wh[co * 40 + kl] = g_whi[co * 512 + kb + kl];
            Wl[co * 40 + kl] = g_wlo[co * 512 + kb + kl];
        }
        __syncthreads();
#pragma unroll
        for (int ks = 0; ks < 2; ks++) {
            int k0 = ks * 16;
            int ar = wm * 16 + (lane >> 2);
            int ac = k0 + (lane & 3) * 2;
            uint32_t ah0 = *(const uint32_t*)&Ah[ar * 40 + ac];
            uint32_t ah1 = *(const uint32_t*)&Ah[(ar + 8) * 40 + ac];
            uint32_t ah2 = *(const uint32_t*)&Ah[ar * 40 + ac + 8];
            uint32_t ah3 = *(const uint32_t*)&Ah[(ar + 8) * 40 + ac + 8];
            uint32_t al0 = *(const uint32_t*)&Al[ar * 40 + ac];
            uint32_t al1 = *(const uint32_t*)&Al[(ar + 8) * 40 + ac];
            uint32_t al2 = *(const uint32_t*)&Al[ar * 40 + ac + 8];
            uint32_t al3 = *(const uint32_t*)&Al[(ar + 8) * 40 + ac + 8];
#pragma unroll
            for (int nt = 0; nt < 8; nt++) {
                int co = wn * 64 + nt * 8 + (lane >> 2);
                int kc = k0 + (lane & 3) * 2;
                uint32_t bh0 = *(const uint32_t*)&Wh[co * 40 + kc];
                uint32_t bh1 = *(const uint32_t*)&Wh[co * 40 + kc + 8];
                uint32_t bl0 = *(const uint32_t*)&Wl[co * 40 + kc];
                uint32_t bl1 = *(const uint32_t*)&Wl[co * 40 + kc + 8];
                MMA_BF16(d[nt], ah0, ah1, ah2, ah3, bh0, bh1);   // hi*hi
                MMA_BF16(d[nt], ah0, ah1, ah2, ah3, bl0, bl1);   // hi*lo
                MMA_BF16(d[nt], al0, al1, al2, al3, bh0, bh1);   // lo*hi
            }
        }
    }
    // epilogue: D[pos][co] -> g_y[(b*128+co)*P1 + pos], relu + bias
    int r = lane >> 2, c2 = (lane & 3) * 2;
    int pos0 = posbase + wm * 16 + r;
    int pos1 = pos0 + 8;
#pragma unroll
    for (int nt = 0; nt < 8; nt++) {
        int co0 = wn * 64 + nt * 8 + c2;
        float bi0 = bias[co0], bi1 = bias[co0 + 1];
        float* y0 = g_y + (b * NHID + co0) * P1;
        float* y1 = y0 + P1;
        if (pos0 < P1) {
            y0[pos0] = fmaxf(d[nt][0] + bi0, 0.f);
            y1[pos0] = fmaxf(d[nt][1] + bi1, 0.f);
        }
        if (pos1 < P1) {
            y0[pos1] = fmaxf(d[nt][2] + bi0, 0.f);
            y1[pos1] = fmaxf(d[nt][3] + bi1, 0.f);
        }
    }
}

// ---------------- dec2: convT 128->3, k4, s2 -> x_recon ----------------
extern __shared__ float sm_d2[];
__global__ void __launch_bounds__(192) k_dec2(const float* __restrict__ w,
                                              const float* __restrict__ bias,
                                              float* __restrict__ out) {
    float* sy = sm_d2;           // [2 rows][128 ci][32 iw] = 8192
    float* sw = sm_d2 + 8192;    // full weights 128*3*16 = 6144
    int b = blockIdx.y, t = blockIdx.x;   // outputs oh = 2t, 2t+1
    int tid = threadIdx.x;
    const float* yb = g_y + b * (NHID * P1);

    for (int e = tid; e < 8192; e += 192) {
        int r = e >> 12;
        int rem = e & 4095;
        int ci = rem >> 5, iw = rem & 31;
        int ih = t - r;
        float v = 0.f;
        if (iw < S1 && (unsigned)ih < (unsigned)S1) v = yb[ci * P1 + ih * S1 + iw];
        sy[e] = v;
    }
    for (int e = tid; e < 6144; e += 192) sw[e] = w[e];
    __syncthreads();

    int co = tid >> 6;      // 0..2
    int ow = tid & 63;
    int pw = ow & 1;
    int iw0 = ow >> 1;
    int iw1 = iw0 - 1;
    bool ok1 = (iw1 >= 0);
    int iw1c = ok1 ? iw1 : 0;

    float accE = 0.f, accO = 0.f;
#pragma unroll 4
    for (int ci = 0; ci < NHID; ci++) {
        float y00 = sy[ci * 32 + iw0];
        float y01 = ok1 ? sy[ci * 32 + iw1c] : 0.f;
        float y10 = sy[4096 + ci * 32 + iw0];
        float y11 = ok1 ? sy[4096 + ci * 32 + iw1c] : 0.f;
        const float* wb = sw + ci * 48 + co * 16;
        accE += y00 * wb[pw]      + y01 * wb[pw + 2]
              + y10 * wb[8 + pw]  + y11 * wb[8 + pw + 2];
        accO += y00 * wb[4 + pw]  + y01 * wb[4 + pw + 2]
              + y10 * wb[12 + pw] + y11 * wb[12 + pw + 2];
    }
    float bi = bias[co];
    int base = b * (3 * 4096) + co * 4096 + (2 * t) * 64 + ow;
    out[base]      = accE + bi;
    out[base + 64] = accO + bi;
}

// ---------------- finalize: loss + perplexity ----------------
__global__ void k_final(float* __restrict__ out) {
    __shared__ double sd[1024];
    int t = threadIdx.x;
    double pr = (double)g_counts[t] / (double)NROWS;
    sd[t] = pr * log(pr + 1e-10);
    __syncthreads();
    for (int s = 512; s > 0; s >>= 1) {
        if (t < s) sd[t] += sd[t + s];
        __syncthreads();
    }
    if (t == 0) {
        out[786432] = (float)(1.25 * g_sse / NELEMF);  // loss = (1+beta)*mse
        out[786433] = (float)exp(-sd[0]);              // perplexity
    }
}

// ---------------- launch ----------------
extern "C" void kernel_launch(void* const* d_in, const int* in_sizes, int n_in,
                              void* d_out, int out_size) {
    const float* x   = (const float*)d_in[0];
    const float* ew1 = (const float*)d_in[1];
    const float* eb1 = (const float*)d_in[2];
    const float* ew2 = (const float*)d_in[3];
    const float* eb2 = (const float*)d_in[4];
    const float* cb  = (const float*)d_in[5];
    const float* dw1 = (const float*)d_in[6];
    const float* db1 = (const float*)d_in[7];
    const float* dw2 = (const float*)d_in[8];
    const float* db2 = (const float*)d_in[9];
    float* out = (float*)d_out;

    cudaFuncSetAttribute(k_vq, cudaFuncAttributeMaxDynamicSharedMemorySize,
                         2 * 128 * 68 * (int)sizeof(float));
    cudaFuncSetAttribute(k_dec2, cudaFuncAttributeMaxDynamicSharedMemorySize,
                         (8192 + 6144) * (int)sizeof(float));

    k_zero<<<1, 1024>>>();
    k_cnorm<<<4, 256>>>(cb);
    k_wsplit<<<256, 256>>>(dw1);
    k_conv1<<<dim3(16, NB), 256>>>(x, ew1, eb1);
    k_conv2<<<dim3(15, NB), 256>>>(ew2, eb2);
    k_znorm<<<NROWS / 64, 256>>>();
    k_vq<<<NROWS / 64, 256, 2 * 128 * 68 * (int)sizeof(float)>>>(cb);
    k_dec1t<<<dim3(16, NB), 256>>>(db1);
    k_dec2<<<dim3(32, NB), 192, (8192 + 6144) * (int)sizeof(float)>>>(dw2, db2, out);
    k_final<<<1, 1024>>>(out);
}

// round 10
// speedup vs baseline: 1.6050x; 1.1550x over previous
#include <cuda_runtime.h>
#include <cuda_bf16.h>
#include <cstdint>
#include <math.h>

// ---------------- problem constants ----------------
#define NB    64
#define NCIN  3
#define NHID  128
#define NK    1024

#define S1    31          // conv1 out spatial
#define P1    961         // 31*31
#define S2    30          // conv2 out spatial
#define P2    900         // 30*30
#define NROWS 57600       // 64*900 flat VQ rows
#define NELEMF 7372800.0  // 64*128*900

#define VQ_ROWS 128
#define VQ_MARGIN 8e-6f

// ---------------- scratch (device globals; no allocation allowed) ----------
__device__ float  g_z1[NB * NHID * P1];   // encoder conv1 out (relu)
__device__ float  g_z [NB * NHID * P2];   // encoder conv2 out (relu) == flat rows
__device__ float  g_q [NB * NHID * P2];   // quantized (== straight-through value)
__device__ float  g_y [NB * NHID * P1];   // dec1 out (relu)
__device__ float  g_cnorm[NK];
__device__ float  g_znorm[NROWS];
__device__ int    g_counts[NK];
__device__ double g_sse;
__device__ __nv_bfloat16 g_whi[NHID * 512];  // dec_w1 split hi, layout [co][k]
__device__ __nv_bfloat16 g_wlo[NHID * 512];  // dec_w1 split lo

// ---------------- mma helper ----------------
#define MMA_BF16(d, a0, a1, a2, a3, b0, b1)                                   \
    asm volatile(                                                             \
        "mma.sync.aligned.m16n8k16.row.col.f32.bf16.bf16.f32 "                \
        "{%0,%1,%2,%3}, {%4,%5,%6,%7}, {%8,%9}, {%0,%1,%2,%3};"               \
        : "+f"(d[0]), "+f"(d[1]), "+f"(d[2]), "+f"(d[3])                      \
        : "r"(a0), "r"(a1), "r"(a2), "r"(a3), "r"(b0), "r"(b1))

#define TOP2(val, idx, v0, v1, i0, i1)                                        \
    if ((val) < (v1)) {                                                       \
        if ((val) < (v0)) { v1 = v0; i1 = i0; v0 = (val); i0 = (idx); }       \
        else              { v1 = (val); i1 = (idx); }                         \
    }

// ---------------- init ----------------
__global__ void k_zero() {
    int t = blockIdx.x * blockDim.x + threadIdx.x;
    if (t < NK) g_counts[t] = 0;
    if (t == 0) g_sse = 0.0;
}

// |c|^2 per code: strict sequential mul/add
__global__ void k_cnorm(const float* __restrict__ cb) {
    int c = blockIdx.x * 256 + threadIdx.x;
    if (c < NK) {
        const float* p = cb + c * NHID;
        float s = 0.f;
        for (int d = 0; d < NHID; d++) {
            float m = __fmul_rn(p[d], p[d]);
            s = __fadd_rn(s, m);
        }
        g_cnorm[c] = s;
    }
}

// |z|^2 per flat row: strict sequential
__global__ void __launch_bounds__(256) k_znorm() {
    __shared__ float s[64 * 129];
    int row0 = blockIdx.x * 64;
    int tid = threadIdx.x;
#pragma unroll
    for (int it = 0; it < 32; it++) {
        int e = tid + 256 * it;
        int r = e >> 7, d = e & 127;
        s[r * 129 + d] = g_z[row0 * NHID + e];
    }
    __syncthreads();
    if (tid < 64) {
        const float* p = s + tid * 129;
        float acc = 0.f;
        for (int d = 0; d < 128; d++) {
            float m = __fmul_rn(p[d], p[d]);
            acc = __fadd_rn(acc, m);
        }
        g_znorm[row0 + tid] = acc;
    }
}

// ---------------- dec_w1 bf16 split: Wt[co][k], k = ci*4 + tap ------------
__global__ void k_wsplit(const float* __restrict__ w) {
    int e = blockIdx.x * 256 + threadIdx.x;   // 65536 elems
    int co = e >> 9, k = e & 511;
    int ci = k >> 2, tap = k & 3;
    float v = w[ci * 512 + co * 4 + tap];
    __nv_bfloat16 h = __float2bfloat16(v);
    g_whi[e] = h;
    g_wlo[e] = __float2bfloat16(v - __bfloat162float(h));
}

// ---------------- conv1: 3->128, k4, s2, relu (smem GEMM, K=48) ----------
__global__ void __launch_bounds__(256) k_conv1(const float* __restrict__ x,
                                               const float* __restrict__ w,
                                               const float* __restrict__ bias) {
    __shared__ __align__(16) float As[48 * 132];   // [k][co]
    __shared__ __align__(16) float Bs[48 * 68];    // [k][pos]
    int b = blockIdx.y;
    int posbase = blockIdx.x * 64;
    int tid = threadIdx.x, tx = tid & 15, ty = tid >> 4;
    const float* xb = x + b * (NCIN * 64 * 64);

    for (int e = tid; e < 48 * 128; e += 256) {
        int co = e / 48, kl = e - co * 48;
        int kh = kl / 12, r2 = kl - kh * 12;
        int kw = r2 / 3, ci = r2 - kw * 3;
        As[kl * 132 + co] = w[co * 48 + ci * 16 + kh * 4 + kw];
    }
    for (int e = tid; e < 48 * 64; e += 256) {
        int pl = e & 63, kl = e >> 6;
        int kh = kl / 12, r2 = kl - kh * 12;
        int kw = r2 / 3, ci = r2 - kw * 3;
        int pos = posbase + pl;
        float v = 0.f;
        if (pos < P1) {
            int oh = pos / S1, ow = pos - oh * S1;
            v = xb[ci * 4096 + (oh * 2 + kh) * 64 + (ow * 2 + kw)];
        }
        Bs[kl * 68 + pl] = v;
    }
    __syncthreads();

    float acc[8][4];
#pragma unroll
    for (int i = 0; i < 8; i++)
#pragma unroll
        for (int j = 0; j < 4; j++) acc[i][j] = 0.f;

#pragma unroll 8
    for (int kl = 0; kl < 48; kl++) {
        float4 a0 = *(const float4*)(As + kl * 132 + 4 * ty);
        float4 a1 = *(const float4*)(As + kl * 132 + 64 + 4 * ty);
        float4 b0 = *(const float4*)(Bs + kl * 68 + 4 * tx);
        float ar[8] = {a0.x, a0.y, a0.z, a0.w, a1.x, a1.y, a1.z, a1.w};
        float br[4] = {b0.x, b0.y, b0.z, b0.w};
#pragma unroll
        for (int i = 0; i < 8; i++)
#pragma unroll
            for (int j = 0; j < 4; j++)
                acc[i][j] = __fmaf_rn(ar[i], br[j], acc[i][j]);
    }
#pragma unroll
    for (int i = 0; i < 8; i++) {
        int co = (i < 4) ? (4 * ty + i) : (64 + 4 * ty + i - 4);
        float bi = bias[co];
        float* zo = g_z1 + (b * NHID + co) * P1;
#pragma unroll
        for (int j = 0; j < 4; j++) {
            int pos = posbase + 4 * tx + j;
            if (pos < P1) zo[pos] = fmaxf(__fadd_rn(acc[i][j], bi), 0.f);
        }
    }
}

// ---------------- conv2: 128->128, k2, s1, relu (exact fp32 GEMM) --------
__global__ void __launch_bounds__(256) k_conv2(const float* __restrict__ w,
                                               const float* __restrict__ bias) {
    __shared__ __align__(16) float As[32 * 132];   // [k'][co]
    __shared__ __align__(16) float Bs[32 * 68];    // [k'][pos]
    int b = blockIdx.y;
    int posbase = blockIdx.x * 64;
    int tid = threadIdx.x, tx = tid & 15, ty = tid >> 4;
    const float* zin = g_z1 + b * (NHID * P1);

    float acc[8][4];
#pragma unroll
    for (int i = 0; i < 8; i++)
#pragma unroll
        for (int j = 0; j < 4; j++) acc[i][j] = 0.f;

    for (int kb = 0; kb < 512; kb += 32) {
        __syncthreads();
#pragma unroll
        for (int it = 0; it < 16; it++) {            // W tile 32x128
            int e = tid + 256 * it;
            int kl = e & 31, co = e >> 5;
            int kk = kb + kl;
            int ci = kk & 127, tap = kk >> 7;
            As[kl * 132 + co] = w[co * 512 + ci * 4 + tap];
        }
#pragma unroll
        for (int it = 0; it < 8; it++) {             // Im tile 32x64
            int e = tid + 256 * it;
            int pl = e & 63, kl = e >> 6;
            int kk = kb + kl;
            int ci = kk & 127, tap = kk >> 7;
            int kh = tap >> 1, kw = tap & 1;
            int pos = posbase + pl;
            float v = 0.f;
            if (pos < P2) {
                int oh = pos / S2, ow = pos - oh * S2;
                v = zin[ci * P1 + (oh + kh) * S1 + ow + kw];
            }
            Bs[kl * 68 + pl] = v;
        }
        __syncthreads();
#pragma unroll 8
        for (int kl = 0; kl < 32; kl++) {
            float4 a0 = *(const float4*)(As + kl * 132 + 4 * ty);
            float4 a1 = *(const float4*)(As + kl * 132 + 64 + 4 * ty);
            float4 b0 = *(const float4*)(Bs + kl * 68 + 4 * tx);
            float ar[8] = {a0.x, a0.y, a0.z, a0.w, a1.x, a1.y, a1.z, a1.w};
            float br[4] = {b0.x, b0.y, b0.z, b0.w};
#pragma unroll
            for (int i = 0; i < 8; i++)
#pragma unroll
                for (int j = 0; j < 4; j++)
                    acc[i][j] = __fmaf_rn(ar[i], br[j], acc[i][j]);
        }
    }
#pragma unroll
    for (int i = 0; i < 8; i++) {
        int co = (i < 4) ? (4 * ty + i) : (64 + 4 * ty + i - 4);
        float bi = bias[co];
        float* zo = g_z + (b * NHID + co) * P2;
#pragma unroll
        for (int j = 0; j < 4; j++) {
            int pos = posbase + 4 * tx + j;
            if (pos < P2) zo[pos] = fmaxf(__fadd_rn(acc[i][j], bi), 0.f);
        }
    }
}

// ---------------- VQ: tensor-core approx + exact repair ------------------
// exact score: M via fma chain k=0..127 ascending, then fl(fl(Z-2M)+C)
__device__ __forceinline__ float vq_exact(int grow, int code, float Z,
                                          const float* __restrict__ cb) {
    const float* zp = g_z + grow * NHID;
    const float* cp = cb + code * NHID;
    float acc = 0.f;
    for (int k = 0; k < NHID; k++) acc = __fmaf_rn(zp[k], cp[k], acc);
    float t = __fmaf_rn(-2.0f, acc, Z);
    return __fadd_rn(t, g_cnorm[code]);
}

extern __shared__ unsigned char sm_raw[];
__global__ void __launch_bounds__(256) k_vqt(const float* __restrict__ cb) {
    __nv_bfloat16* Ah = (__nv_bfloat16*)sm_raw;          // [128 rows][136]
    __nv_bfloat16* Al = Ah + 128 * 136;
    __nv_bfloat16* Bh = Al + 128 * 136;                  // [64 codes][136]
    __nv_bfloat16* Bl = Bh + 64 * 136;
    float* cns  = (float*)(Bl + 64 * 136);               // 1024
    int*   scode = (int*)(cns + 1024);                   // 128
    float* lred = (float*)(scode + 128);                 // 256

    int row0 = blockIdx.x * VQ_ROWS;
    int tid = threadIdx.x, warp = tid >> 5, lane = tid & 31;
    const float* zrow = g_z + row0 * NHID;

    // load z tile -> bf16 hi/lo (resident whole kernel)
#pragma unroll 4
    for (int it = 0; it < 64; it++) {
        int e = tid + 256 * it;        // 16384
        int r = e >> 7, d = e & 127;
        float v = zrow[e];
        __nv_bfloat16 h = __float2bfloat16(v);
        Ah[r * 136 + d] = h;
        Al[r * 136 + d] = __float2bfloat16(v - __bfloat162float(h));
    }
#pragma unroll
    for (int it = 0; it < 4; it++) cns[tid + 256 * it] = g_cnorm[tid + 256 * it];

    int m0 = warp * 16;
    int g = lane >> 2, cg = lane & 3;
    int r0 = m0 + g, r1 = r0 + 8;
    float Z0 = g_znorm[row0 + r0];
    float Z1 = g_znorm[row0 + r1];

    float v0a = 3.4e38f, v1a = 3.4e38f; int i0a = 0, i1a = 0;   // row r0 top2
    float v0b = 3.4e38f, v1b = 3.4e38f; int i0b = 0, i1b = 0;   // row r1 top2

    for (int c0 = 0; c0 < NK; c0 += 64) {
        __syncthreads();
#pragma unroll 4
        for (int it = 0; it < 32; it++) {
            int e = tid + 256 * it;    // 8192
            int c = e >> 7, d = e & 127;
            float v = cb[(c0 + c) * NHID + d];
            __nv_bfloat16 h = __float2bfloat16(v);
            Bh[c * 136 + d] = h;
            Bl[c * 136 + d] = __float2bfloat16(v - __bfloat162float(h));
        }
        __syncthreads();

        float dacc[8][4];
#pragma unroll
        for (int nt = 0; nt < 8; nt++)
#pragma unroll
            for (int j = 0; j < 4; j++) dacc[nt][j] = 0.f;

#pragma unroll
        for (int ks = 0; ks < 8; ks++) {
            int ac = ks * 16 + cg * 2;
            uint32_t ah0 = *(const uint32_t*)&Ah[r0 * 136 + ac];
            uint32_t ah1 = *(const uint32_t*)&Ah[r1 * 136 + ac];
            uint32_t ah2 = *(const uint32_t*)&Ah[r0 * 136 + ac + 8];
            uint32_t ah3 = *(const uint32_t*)&Ah[r1 * 136 + ac + 8];
            uint32_t al0 = *(const uint32_t*)&Al[r0 * 136 + ac];
            uint32_t al1 = *(const uint32_t*)&Al[r1 * 136 + ac];
            uint32_t al2 = *(const uint32_t*)&Al[r0 * 136 + ac + 8];
            uint32_t al3 = *(const uint32_t*)&Al[r1 * 136 + ac + 8];
#pragma unroll
            for (int nt = 0; nt < 8; nt++) {
                int cr = (nt * 8 + g) * 136 + ac;
                uint32_t bh0 = *(const uint32_t*)&Bh[cr];
                uint32_t bh1 = *(const uint32_t*)&Bh[cr + 8];
                uint32_t bl0 = *(const uint32_t*)&Bl[cr];
                uint32_t bl1 = *(const uint32_t*)&Bl[cr + 8];
                MMA_BF16(dacc[nt], ah0, ah1, ah2, ah3, bh0, bh1);
                MMA_BF16(dacc[nt], ah0, ah1, ah2, ah3, bl0, bl1);
                MMA_BF16(dacc[nt], al0, al1, al2, al3, bh0, bh1);
            }
        }
        // approx scores + per-lane top2 per row
#pragma unroll
        for (int nt = 0; nt < 8; nt++) {
            int cA = c0 + nt * 8 + cg * 2;
            float cnA = cns[cA - c0 + c0];   // cns indexed by global code
            float cnB = cns[cA + 1];
            cnA = cns[cA];
            float s00 = __fmaf_rn(-2.f, dacc[nt][0], Z0) + cnA;
            float s01 = __fmaf_rn(-2.f, dacc[nt][1], Z0) + cnB;
            float s10 = __fmaf_rn(-2.f, dacc[nt][2], Z1) + cnA;
            float s11 = __fmaf_rn(-2.f, dacc[nt][3], Z1) + cnB;
            TOP2(s00, cA,     v0a, v1a, i0a, i1a);
            TOP2(s01, cA + 1, v0a, v1a, i0a, i1a);
            TOP2(s10, cA,     v0b, v1b, i0b, i1b);
            TOP2(s11, cA + 1, v0b, v1b, i0b, i1b);
        }
    }

    // approx row-min across the 4 lanes sharing each row
    float rma = v0a, rmb = v0b;
#pragma unroll
    for (int off = 1; off < 4; off <<= 1) {
        rma = fminf(rma, __shfl_xor_sync(0xffffffffu, rma, off));
        rmb = fminf(rmb, __shfl_xor_sync(0xffffffffu, rmb, off));
    }

    // candidates -> exact recompute -> lexicographic exact argmin
    float esa = 3.4e38f; int eia = 0x7fffffff;
    float esb = 3.4e38f; int eib = 0x7fffffff;
    if (v0a <= rma + VQ_MARGIN) {
        float s = vq_exact(row0 + r0, i0a, Z0, cb);
        esa = s; eia = i0a;
    }
    if (v1a <= rma + VQ_MARGIN) {
        float s = vq_exact(row0 + r0, i1a, Z0, cb);
        if (s < esa || (s == esa && i1a < eia)) { esa = s; eia = i1a; }
    }
    if (v0b <= rmb + VQ_MARGIN) {
        float s = vq_exact(row0 + r1, i0b, Z1, cb);
        esb = s; eib = i0b;
    }
    if (v1b <= rmb + VQ_MARGIN) {
        float s = vq_exact(row0 + r1, i1b, Z1, cb);
        if (s < esb || (s == esb && i1b < eib)) { esb = s; eib = i1b; }
    }
#pragma unroll
    for (int off = 1; off < 4; off <<= 1) {
        float ov = __shfl_xor_sync(0xffffffffu, esa, off);
        int   oi = __shfl_xor_sync(0xffffffffu, eia, off);
        if (ov < esa || (ov == esa && oi < eia)) { esa = ov; eia = oi; }
        ov = __shfl_xor_sync(0xffffffffu, esb, off);
        oi = __shfl_xor_sync(0xffffffffu, eib, off);
        if (ov < esb || (ov == esb && oi < eib)) { esb = ov; eib = oi; }
    }
    if (cg == 0) {
        scode[r0] = eia;
        scode[r1] = eib;
        atomicAdd(&g_counts[eia], 1);
        atomicAdd(&g_counts[eib], 1);
    }
    __syncthreads();

    // gather quantized rows + squared-error partial
    float lsum = 0.f;
    float* qout = g_q + row0 * NHID;
#pragma unroll 4
    for (int it = 0; it < 64; it++) {
        int e = tid + 256 * it;
        int r = e >> 7, d = e & 127;
        int code = scode[r];
        float qv = __ldg(&cb[code * NHID + d]);
        float zv = zrow[e];
        qout[e] = qv;
        float df = qv - zv;
        lsum += df * df;
    }
    lred[tid] = lsum;
    __syncthreads();
    for (int s = 128; s > 0; s >>= 1) {
        if (tid < s) lred[tid] += lred[tid + s];
        __syncthreads();
    }
    if (tid == 0) atomicAdd(&g_sse, (double)lred[0]);
}

// ---------------- dec1: convT 128->128, k2, s1, relu -- TENSOR CORES -----
__global__ void __launch_bounds__(256) k_dec1t(const float* __restrict__ bias) {
    __shared__ __align__(16) __nv_bfloat16 Ah[64 * 40];    // [pos][k] +pad
    __shared__ __align__(16) __nv_bfloat16 Al[64 * 40];
    __shared__ __align__(16) __nv_bfloat16 Wh[128 * 40];   // [co][k] +pad
    __shared__ __align__(16) __nv_bfloat16 Wl[128 * 40];
    int b = blockIdx.y;
    int posbase = blockIdx.x * 64;
    int tid = threadIdx.x;
    int warp = tid >> 5, lane = tid & 31;
    int wm = warp >> 1, wn = warp & 1;          // 4 M-tiles x 2 N-halves
    const float* qin = g_q + b * (NHID * P2);

    float d[8][4];
#pragma unroll
    for (int i = 0; i < 8; i++)
#pragma unroll
        for (int j = 0; j < 4; j++) d[i][j] = 0.f;

    for (int kb = 0; kb < 512; kb += 32) {
        __syncthreads();
        // A tile: 64 pos x 32 k (im2col of q, fp32 -> hi/lo bf16)
#pragma unroll
        for (int it = 0; it < 8; it++) {
            int e = tid + 256 * it;             // 2048 = 64*32
            int pl = e & 63, kl = e >> 6;
            int k = kb + kl;
            int ci = k >> 2, kh = (k >> 1) & 1, kw = k & 1;
            int pos = posbase + pl;
            float v = 0.f;
            if (pos < P1) {
                int oh = pos / S1, ow = pos - oh * S1;
                int ih = oh - kh, iw = ow - kw;
                if ((unsigned)ih < (unsigned)S2 && (unsigned)iw < (unsigned)S2)
                    v = qin[ci * P2 + ih * S2 + iw];
            }
            __nv_bfloat16 h = __float2bfloat16(v);
            Ah[pl * 40 + kl] = h;
            Al[pl * 40 + kl] = __float2bfloat16(v - __bfloat162float(h));
        }
        // W tile: 128 co x 32 k (pre-split)
#pragma unroll
        for (int it = 0; it < 16; it++) {
            int e = tid + 256 * it;             // 4096 = 128*32
            int kl = e & 31, co = e >> 5;
            Wh[co * 40 + kl] = g_whi[co * 512 + kb + kl];
            Wl[co * 40 + kl] = g_wlo[co * 512 + kb + kl];
        }
        __syncthreads();
#pragma unroll
        for (int ks = 0; ks < 2; ks++) {
            int k0 = ks * 16;
            int ar = wm * 16 + (lane >> 2);
            int ac = k0 + (lane & 3) * 2;
            uint32_t ah0 = *(const uint32_t*)&Ah[ar * 40 + ac];
            uint32_t ah1 = *(const uint32_t*)&Ah[(ar + 8) * 40 + ac];
            uint32_t ah2 = *(const uint32_t*)&Ah[ar * 40 + ac + 8];
            uint32_t ah3 = *(const uint32_t*)&Ah[(ar + 8) * 40 + ac + 8];
            uint32_t al0 = *(const uint32_t*)&Al[ar * 40 + ac];
            uint32_t al1 = *(const uint32_t*)&Al[(ar + 8) * 40 + ac];
            uint32_t al2 = *(const uint32_t*)&Al[ar * 40 + ac + 8];
            uint32_t al3 = *(const uint32_t*)&Al[(ar + 8) * 40 + ac + 8];
#pragma unroll
            for (int nt = 0; nt < 8; nt++) {
                int co = wn * 64 + nt * 8 + (lane >> 2);
                int kc = k0 + (lane & 3) * 2;
                uint32_t bh0 = *(const uint32_t*)&Wh[co * 40 + kc];
                uint32_t bh1 = *(const uint32_t*)&Wh[co * 40 + kc + 8];
                uint32_t bl0 = *(const uint32_t*)&Wl[co * 40 + kc];
                uint32_t bl1 = *(const uint32_t*)&Wl[co * 40 + kc + 8];
                MMA_BF16(d[nt], ah0, ah1, ah2, ah3, bh0, bh1);   // hi*hi
                MMA_BF16(d[nt], ah0, ah1, ah2, ah3, bl0, bl1);   // hi*lo
                MMA_BF16(d[nt], al0, al1, al2, al3, bh0, bh1);   // lo*hi
            }
        }
    }
    // epilogue: D[pos][co] -> g_y[(b*128+co)*P1 + pos], relu + bias
    int r = lane >> 2, c2 = (lane & 3) * 2;
    int pos0 = posbase + wm * 16 + r;
    int pos1 = pos0 + 8;
#pragma unroll
    for (int nt = 0; nt < 8; nt++) {
        int co0 = wn * 64 + nt * 8 + c2;
        float bi0 = bias[co0], bi1 = bias[co0 + 1];
        float* y0 = g_y + (b * NHID + co0) * P1;
        float* y1 = y0 + P1;
        if (pos0 < P1) {
            y0[pos0] = fmaxf(d[nt][0] + bi0, 0.f);
            y1[pos0] = fmaxf(d[nt][1] + bi1, 0.f);
        }
        if (pos1 < P1) {
            y0[pos1] = fmaxf(d[nt][2] + bi0, 0.f);
            y1[pos1] = fmaxf(d[nt][3] + bi1, 0.f);
        }
    }
}

// ---------------- dec2: convT 128->3, k4, s2 -> x_recon ----------------
extern __shared__ float sm_d2[];
__global__ void __launch_bounds__(192) k_dec2(const float* __restrict__ w,
                                              const float* __restrict__ bias,
                                              float* __restrict__ out) {
    float* sy = sm_d2;           // [2 rows][128 ci][32 iw] = 8192
    float* sw = sm_d2 + 8192;    // full weights 128*3*16 = 6144
    int b = blockIdx.y, t = blockIdx.x;   // outputs oh = 2t, 2t+1
    int tid = threadIdx.x;
    const float* yb = g_y + b * (NHID * P1);

    for (int e = tid; e < 8192; e += 192) {
        int r = e >> 12;
        int rem = e & 4095;
        int ci = rem >> 5, iw = rem & 31;
        int ih = t - r;
        float v = 0.f;
        if (iw < S1 && (unsigned)ih < (unsigned)S1) v = yb[ci * P1 + ih * S1 + iw];
        sy[e] = v;
    }
    for (int e = tid; e < 6144; e += 192) sw[e] = w[e];
    __syncthreads();

    int co = tid >> 6;      // 0..2
    int ow = tid & 63;
    int pw = ow & 1;
    int iw0 = ow >> 1;
    int iw1 = iw0 - 1;
    bool ok1 = (iw1 >= 0);
    int iw1c = ok1 ? iw1 : 0;

    float accE = 0.f, accO = 0.f;
#pragma unroll 4
    for (int ci = 0; ci < NHID; ci++) {
        float y00 = sy[ci * 32 + iw0];
        float y01 = ok1 ? sy[ci * 32 + iw1c] : 0.f;
        float y10 = sy[4096 + ci * 32 + iw0];
        float y11 = ok1 ? sy[4096 + ci * 32 + iw1c] : 0.f;
        const float* wb = sw + ci * 48 + co * 16;
        accE += y00 * wb[pw]      + y01 * wb[pw + 2]
              + y10 * wb[8 + pw]  + y11 * wb[8 + pw + 2];
        accO += y00 * wb[4 + pw]  + y01 * wb[4 + pw + 2]
              + y10 * wb[12 + pw] + y11 * wb[12 + pw + 2];
    }
    float bi = bias[co];
    int base = b * (3 * 4096) + co * 4096 + (2 * t) * 64 + ow;
    out[base]      = accE + bi;
    out[base + 64] = accO + bi;
}

// ---------------- finalize: loss + perplexity ----------------
__global__ void k_final(float* __restrict__ out) {
    __shared__ double sd[1024];
    int t = threadIdx.x;
    double pr = (double)g_counts[t] / (double)NROWS;
    sd[t] = pr * log(pr + 1e-10);
    __syncthreads();
    for (int s = 512; s > 0; s >>= 1) {
        if (t < s) sd[t] += sd[t + s];
        __syncthreads();
    }
    if (t == 0) {
        out[786432] = (float)(1.25 * g_sse / NELEMF);  // loss = (1+beta)*mse
        out[786433] = (float)exp(-sd[0]);              // perplexity
    }
}

// ---------------- launch ----------------
extern "C" void kernel_launch(void* const* d_in, const int* in_sizes, int n_in,
                              void* d_out, int out_size) {
    const float* x   = (const float*)d_in[0];
    const float* ew1 = (const float*)d_in[1];
    const float* eb1 = (const float*)d_in[2];
    const float* ew2 = (const float*)d_in[3];
    const float* eb2 = (const float*)d_in[4];
    const float* cb  = (const float*)d_in[5];
    const float* dw1 = (const float*)d_in[6];
    const float* db1 = (const float*)d_in[7];
    const float* dw2 = (const float*)d_in[8];
    const float* db2 = (const float*)d_in[9];
    float* out = (float*)d_out;

    // k_vqt dynamic smem: Ah/Al 2*128*136*2 + Bh/Bl 2*64*136*2 + cns 4096
    //                     + scode 512 + lred 1024
    int vq_smem = 2 * 128 * 136 * 2 + 2 * 64 * 136 * 2 + 4096 + 512 + 1024;
    cudaFuncSetAttribute(k_vqt, cudaFuncAttributeMaxDynamicSharedMemorySize,
                         vq_smem);
    cudaFuncSetAttribute(k_dec2, cudaFuncAttributeMaxDynamicSharedMemorySize,
                         (8192 + 6144) * (int)sizeof(float));

    k_zero<<<1, 1024>>>();
    k_cnorm<<<4, 256>>>(cb);
    k_wsplit<<<256, 256>>>(dw1);
    k_conv1<<<dim3(16, NB), 256>>>(x, ew1, eb1);
    k_conv2<<<dim3(15, NB), 256>>>(ew2, eb2);
    k_znorm<<<NROWS / 64, 256>>>();
    k_vqt<<<NROWS / VQ_ROWS, 256, vq_smem>>>(cb);
    k_dec1t<<<dim3(16, NB), 256>>>(db1);
    k_dec2<<<dim3(32, NB), 192, (8192 + 6144) * (int)sizeof(float)>>>(dw2, db2, out);
    k_final<<<1, 1024>>>(out);
}

// round 11
// speedup vs baseline: 1.8106x; 1.1281x over previous
#include <cuda_runtime.h>
#include <cuda_bf16.h>
#include <cstdint>
#include <math.h>

// ---------------- problem constants ----------------
#define NB    64
#define NCIN  3
#define NHID  128
#define NK    1024

#define S1    31          // conv1 out spatial
#define P1    961         // 31*31
#define S2    30          // conv2 out spatial
#define P2    900         // 30*30
#define NROWS 57600       // 64*900 flat VQ rows
#define NELEMF 7372800.0  // 64*128*900

#define VQ_ROWS 128
#define VQ_MARGIN 8e-6f

// ---------------- scratch (device globals; no allocation allowed) ----------
__device__ float  g_z1[NB * NHID * P1];   // encoder conv1 out (relu)
__device__ float  g_z [NB * NHID * P2];   // encoder conv2 out (relu) == flat rows
__device__ float  g_y [NB * NHID * P1];   // dec1 out (relu)
__device__ float  g_cnorm[NK];
__device__ float  g_znorm[NROWS];
__device__ int    g_counts[NK];
__device__ double g_sse;
__device__ __nv_bfloat16 g_whi[NHID * 512];   // dec_w1 split hi, layout [co][k]
__device__ __nv_bfloat16 g_wlo[NHID * 512];   // dec_w1 split lo
__device__ __nv_bfloat16 g_cbhi[NK * NHID];   // codebook split hi [code][d]
__device__ __nv_bfloat16 g_cblo[NK * NHID];
__device__ __nv_bfloat16 g_qhi[NB * NHID * P2];  // quantized split (dec1 A input)
__device__ __nv_bfloat16 g_qlo[NB * NHID * P2];

// ---------------- helpers ----------------
#define MMA_BF16(d, a0, a1, a2, a3, b0, b1)                                   \
    asm volatile(                                                             \
        "mma.sync.aligned.m16n8k16.row.col.f32.bf16.bf16.f32 "                \
        "{%0,%1,%2,%3}, {%4,%5,%6,%7}, {%8,%9}, {%0,%1,%2,%3};"               \
        : "+f"(d[0]), "+f"(d[1]), "+f"(d[2]), "+f"(d[3])                      \
        : "r"(a0), "r"(a1), "r"(a2), "r"(a3), "r"(b0), "r"(b1))

#define TOP2(val, idx, v0, v1, i0, i1)                                        \
    if ((val) < (v1)) {                                                       \
        if ((val) < (v0)) { v1 = v0; i1 = i0; v0 = (val); i0 = (idx); }       \
        else              { v1 = (val); i1 = (idx); }                         \
    }

__device__ __forceinline__ void cp_async16(void* dst, const void* src) {
    unsigned s = (unsigned)__cvta_generic_to_shared(dst);
    asm volatile("cp.async.ca.shared.global [%0], [%1], 16;" :: "r"(s), "l"(src));
}
#define CP_COMMIT asm volatile("cp.async.commit_group;")
#define CP_WAIT1  asm volatile("cp.async.wait_group 1;")
#define CP_WAIT0  asm volatile("cp.async.wait_group 0;")

// ---------------- prep: zero + cnorm + wsplit + cbsplit (one kernel) -----
__global__ void k_prep(const float* __restrict__ cb,
                       const float* __restrict__ dw1) {
    int e = blockIdx.x * 256 + threadIdx.x;   // 131072 threads
    if (e < NK * NHID) {
        float v = cb[e];
        __nv_bfloat16 h = __float2bfloat16(v);
        g_cbhi[e] = h;
        g_cblo[e] = __float2bfloat16(v - __bfloat162float(h));
    }
    if (e < NHID * 512) {
        int co = e >> 9, k = e & 511;
        int ci = k >> 2, tap = k & 3;
        float v = dw1[ci * 512 + co * 4 + tap];
        __nv_bfloat16 h = __float2bfloat16(v);
        g_whi[e] = h;
        g_wlo[e] = __float2bfloat16(v - __bfloat162float(h));
    }
    if (e < NK) {
        g_counts[e] = 0;
        const float* p = cb + e * NHID;
        float s = 0.f;
        for (int d = 0; d < NHID; d++) {
            float m = __fmul_rn(p[d], p[d]);
            s = __fadd_rn(s, m);
        }
        g_cnorm[e] = s;
    }
    if (e == 0) g_sse = 0.0;
}

// ---------------- |z|^2 per flat row: strict sequential ------------------
__global__ void __launch_bounds__(256) k_znorm() {
    __shared__ float s[64 * 129];
    int row0 = blockIdx.x * 64;
    int tid = threadIdx.x;
#pragma unroll
    for (int it = 0; it < 32; it++) {
        int e = tid + 256 * it;
        int r = e >> 7, d = e & 127;
        s[r * 129 + d] = g_z[row0 * NHID + e];
    }
    __syncthreads();
    if (tid < 64) {
        const float* p = s + tid * 129;
        float acc = 0.f;
        for (int d = 0; d < 128; d++) {
            float m = __fmul_rn(p[d], p[d]);
            acc = __fadd_rn(acc, m);
        }
        g_znorm[row0 + tid] = acc;
    }
}

// ---------------- conv1: 3->128, k4, s2, relu (smem GEMM, K=48) ----------
__global__ void __launch_bounds__(256) k_conv1(const float* __restrict__ x,
                                               const float* __restrict__ w,
                                               const float* __restrict__ bias) {
    __shared__ __align__(16) float As[48 * 132];   // [k][co]
    __shared__ __align__(16) float Bs[48 * 68];    // [k][pos]
    int b = blockIdx.y;
    int posbase = blockIdx.x * 64;
    int tid = threadIdx.x, tx = tid & 15, ty = tid >> 4;
    const float* xb = x + b * (NCIN * 64 * 64);

    for (int e = tid; e < 48 * 128; e += 256) {
        int co = e / 48, kl = e - co * 48;
        int kh = kl / 12, r2 = kl - kh * 12;
        int kw = r2 / 3, ci = r2 - kw * 3;
        As[kl * 132 + co] = w[co * 48 + ci * 16 + kh * 4 + kw];
    }
    for (int e = tid; e < 48 * 64; e += 256) {
        int pl = e & 63, kl = e >> 6;
        int kh = kl / 12, r2 = kl - kh * 12;
        int kw = r2 / 3, ci = r2 - kw * 3;
        int pos = posbase + pl;
        float v = 0.f;
        if (pos < P1) {
            int oh = pos / S1, ow = pos - oh * S1;
            v = xb[ci * 4096 + (oh * 2 + kh) * 64 + (ow * 2 + kw)];
        }
        Bs[kl * 68 + pl] = v;
    }
    __syncthreads();

    float acc[8][4];
#pragma unroll
    for (int i = 0; i < 8; i++)
#pragma unroll
        for (int j = 0; j < 4; j++) acc[i][j] = 0.f;

#pragma unroll 8
    for (int kl = 0; kl < 48; kl++) {
        float4 a0 = *(const float4*)(As + kl * 132 + 4 * ty);
        float4 a1 = *(const float4*)(As + kl * 132 + 64 + 4 * ty);
        float4 b0 = *(const float4*)(Bs + kl * 68 + 4 * tx);
        float ar[8] = {a0.x, a0.y, a0.z, a0.w, a1.x, a1.y, a1.z, a1.w};
        float br[4] = {b0.x, b0.y, b0.z, b0.w};
#pragma unroll
        for (int i = 0; i < 8; i++)
#pragma unroll
            for (int j = 0; j < 4; j++)
                acc[i][j] = __fmaf_rn(ar[i], br[j], acc[i][j]);
    }
#pragma unroll
    for (int i = 0; i < 8; i++) {
        int co = (i < 4) ? (4 * ty + i) : (64 + 4 * ty + i - 4);
        float bi = bias[co];
        float* zo = g_z1 + (b * NHID + co) * P1;
#pragma unroll
        for (int j = 0; j < 4; j++) {
            int pos = posbase + 4 * tx + j;
            if (pos < P1) zo[pos] = fmaxf(__fadd_rn(acc[i][j], bi), 0.f);
        }
    }
}

// ---------------- conv2: 128->128, k2, s1, relu (exact fp32 GEMM) --------
__global__ void __launch_bounds__(256) k_conv2(const float* __restrict__ w,
                                               const float* __restrict__ bias) {
    __shared__ __align__(16) float As[32 * 132];   // [k'][co]
    __shared__ __align__(16) float Bs[32 * 68];    // [k'][pos]
    int b = blockIdx.y;
    int posbase = blockIdx.x * 64;
    int tid = threadIdx.x, tx = tid & 15, ty = tid >> 4;
    const float* zin = g_z1 + b * (NHID * P1);

    float acc[8][4];
#pragma unroll
    for (int i = 0; i < 8; i++)
#pragma unroll
        for (int j = 0; j < 4; j++) acc[i][j] = 0.f;

    for (int kb = 0; kb < 512; kb += 32) {
        __syncthreads();
#pragma unroll
        for (int it = 0; it < 16; it++) {            // W tile 32x128
            int e = tid + 256 * it;
            int kl = e & 31, co = e >> 5;
            int kk = kb + kl;
            int ci = kk & 127, tap = kk >> 7;
            As[kl * 132 + co] = w[co * 512 + ci * 4 + tap];
        }
#pragma unroll
        for (int it = 0; it < 8; it++) {             // Im tile 32x64
            int e = tid + 256 * it;
            int pl = e & 63, kl = e >> 6;
            int kk = kb + kl;
            int ci = kk & 127, tap = kk >> 7;
            int kh = tap >> 1, kw = tap & 1;
            int pos = posbase + pl;
            float v = 0.f;
            if (pos < P2) {
                int oh = pos / S2, ow = pos - oh * S2;
                v = zin[ci * P1 + (oh + kh) * S1 + ow + kw];
            }
            Bs[kl * 68 + pl] = v;
        }
        __syncthreads();
#pragma unroll 8
        for (int kl = 0; kl < 32; kl++) {
            float4 a0 = *(const float4*)(As + kl * 132 + 4 * ty);
            float4 a1 = *(const float4*)(As + kl * 132 + 64 + 4 * ty);
            float4 b0 = *(const float4*)(Bs + kl * 68 + 4 * tx);
            float ar[8] = {a0.x, a0.y, a0.z, a0.w, a1.x, a1.y, a1.z, a1.w};
            float br[4] = {b0.x, b0.y, b0.z, b0.w};
#pragma unroll
            for (int i = 0; i < 8; i++)
#pragma unroll
                for (int j = 0; j < 4; j++)
                    acc[i][j] = __fmaf_rn(ar[i], br[j], acc[i][j]);
        }
    }
#pragma unroll
    for (int i = 0; i < 8; i++) {
        int co = (i < 4) ? (4 * ty + i) : (64 + 4 * ty + i - 4);
        float bi = bias[co];
        float* zo = g_z + (b * NHID + co) * P2;
#pragma unroll
        for (int j = 0; j < 4; j++) {
            int pos = posbase + 4 * tx + j;
            if (pos < P2) zo[pos] = fmaxf(__fadd_rn(acc[i][j], bi), 0.f);
        }
    }
}

// ---------------- VQ: tensor-core approx + exact repair ------------------
__device__ __forceinline__ float vq_exact(int grow, int code, float Z,
                                          const float* __restrict__ cb) {
    const float* zp = g_z + grow * NHID;
    const float* cp = cb + code * NHID;
    float acc = 0.f;
    for (int k = 0; k < NHID; k++) acc = __fmaf_rn(zp[k], cp[k], acc);
    float t = __fmaf_rn(-2.0f, acc, Z);
    return __fadd_rn(t, g_cnorm[code]);
}

extern __shared__ unsigned char sm_raw[];
__global__ void __launch_bounds__(256) k_vqt(const float* __restrict__ cb) {
    __nv_bfloat16* Ah = (__nv_bfloat16*)sm_raw;          // [128 rows][136]
    __nv_bfloat16* Al = Ah + 128 * 136;
    __nv_bfloat16* Bh = Al + 128 * 136;                  // [2 bufs][64][136]
    __nv_bfloat16* Bl = Bh + 2 * 64 * 136;
    float* cns   = (float*)(Bl + 2 * 64 * 136);          // 1024
    int*   scode = (int*)(cns + NK);                     // 128
    float* lred  = (float*)(scode + VQ_ROWS);            // 256

    int row0 = blockIdx.x * VQ_ROWS;
    int tid = threadIdx.x, warp = tid >> 5, lane = tid & 31;
    const float* zrow = g_z + row0 * NHID;

    // z tile -> bf16 hi/lo (resident whole kernel; once per block)
#pragma unroll 4
    for (int it = 0; it < 64; it++) {
        int e = tid + 256 * it;        // 16384
        int r = e >> 7, d = e & 127;
        float v = zrow[e];
        __nv_bfloat16 h = __float2bfloat16(v);
        Ah[r * 136 + d] = h;
        Al[r * 136 + d] = __float2bfloat16(v - __bfloat162float(h));
    }
#pragma unroll
    for (int it = 0; it < 4; it++) cns[tid + 256 * it] = g_cnorm[tid + 256 * it];

    int m0 = warp * 16;
    int g = lane >> 2, cg = lane & 3;
    int r0 = m0 + g, r1 = r0 + 8;
    float Z0 = g_znorm[row0 + r0];
    float Z1 = g_znorm[row0 + r1];

    float v0a = 3.4e38f, v1a = 3.4e38f; int i0a = 0, i1a = 0;
    float v0b = 3.4e38f, v1b = 3.4e38f; int i0b = 0, i1b = 0;

    // --- codebook chunk copy via cp.async (pre-split bf16 -> smem) ---
    // chunk = 64 codes; per half 1024 x 16B; 8 cp.async / thread
#define VQ_ISSUE(c0_, buf_) {                                                  \
        int base_ = (c0_) * NHID;                                              \
        __nv_bfloat16* bhd = Bh + (buf_) * (64 * 136);                         \
        __nv_bfloat16* bld = Bl + (buf_) * (64 * 136);                         \
        _Pragma("unroll")                                                      \
        for (int it = 0; it < 8; it++) {                                       \
            int e = tid + 256 * it;                                            \
            int half = e >> 10, u = e & 1023;                                  \
            int r = u >> 4, seg = u & 15;                                      \
            const __nv_bfloat16* src =                                         \
                (half ? g_cblo : g_cbhi) + base_ + r * NHID + seg * 8;         \
            __nv_bfloat16* dst = (half ? bld : bhd) + r * 136 + seg * 8;       \
            cp_async16(dst, src);                                              \
        }                                                                      \
    }

    VQ_ISSUE(0, 0); CP_COMMIT;

    for (int cc = 0; cc < 16; cc++) {
        int buf = cc & 1;
        int c0 = cc * 64;
        if (cc + 1 < 16) { VQ_ISSUE((cc + 1) * 64, (cc + 1) & 1); CP_COMMIT; CP_WAIT1; }
        else { CP_WAIT0; }
        __syncthreads();

        const __nv_bfloat16* Bhb = Bh + buf * (64 * 136);
        const __nv_bfloat16* Blb = Bl + buf * (64 * 136);

        float dacc[8][4];
#pragma unroll
        for (int nt = 0; nt < 8; nt++)
#pragma unroll
            for (int j = 0; j < 4; j++) dacc[nt][j] = 0.f;

#pragma unroll
        for (int ks = 0; ks < 8; ks++) {
            int ac = ks * 16 + cg * 2;
            uint32_t ah0 = *(const uint32_t*)&Ah[r0 * 136 + ac];
            uint32_t ah1 = *(const uint32_t*)&Ah[r1 * 136 + ac];
            uint32_t ah2 = *(const uint32_t*)&Ah[r0 * 136 + ac + 8];
            uint32_t ah3 = *(const uint32_t*)&Ah[r1 * 136 + ac + 8];
            uint32_t al0 = *(const uint32_t*)&Al[r0 * 136 + ac];
            uint32_t al1 = *(const uint32_t*)&Al[r1 * 136 + ac];
            uint32_t al2 = *(const uint32_t*)&Al[r0 * 136 + ac + 8];
            uint32_t al3 = *(const uint32_t*)&Al[r1 * 136 + ac + 8];
#pragma unroll
            for (int nt = 0; nt < 8; nt++) {
                int cr = (nt * 8 + g) * 136 + ac;
                uint32_t bh0 = *(const uint32_t*)&Bhb[cr];
                uint32_t bh1 = *(const uint32_t*)&Bhb[cr + 8];
                uint32_t bl0 = *(const uint32_t*)&Blb[cr];
                uint32_t bl1 = *(const uint32_t*)&Blb[cr + 8];
                MMA_BF16(dacc[nt], ah0, ah1, ah2, ah3, bh0, bh1);
                MMA_BF16(dacc[nt], ah0, ah1, ah2, ah3, bl0, bl1);
                MMA_BF16(dacc[nt], al0, al1, al2, al3, bh0, bh1);
            }
        }
#pragma unroll
        for (int nt = 0; nt < 8; nt++) {
            int cA = c0 + nt * 8 + cg * 2;
            float cnA = cns[cA];
            float cnB = cns[cA + 1];
            float s00 = __fmaf_rn(-2.f, dacc[nt][0], Z0) + cnA;
            float s01 = __fmaf_rn(-2.f, dacc[nt][1], Z0) + cnB;
            float s10 = __fmaf_rn(-2.f, dacc[nt][2], Z1) + cnA;
            float s11 = __fmaf_rn(-2.f, dacc[nt][3], Z1) + cnB;
            TOP2(s00, cA,     v0a, v1a, i0a, i1a);
            TOP2(s01, cA + 1, v0a, v1a, i0a, i1a);
            TOP2(s10, cA,     v0b, v1b, i0b, i1b);
            TOP2(s11, cA + 1, v0b, v1b, i0b, i1b);
        }
        __syncthreads();
    }
#undef VQ_ISSUE

    // approx row-min across the 4 lanes sharing each row
    float rma = v0a, rmb = v0b;
#pragma unroll
    for (int off = 1; off < 4; off <<= 1) {
        rma = fminf(rma, __shfl_xor_sync(0xffffffffu, rma, off));
        rmb = fminf(rmb, __shfl_xor_sync(0xffffffffu, rmb, off));
    }

    // candidates -> exact recompute -> lexicographic exact argmin
    float esa = 3.4e38f; int eia = 0x7fffffff;
    float esb = 3.4e38f; int eib = 0x7fffffff;
    if (v0a <= rma + VQ_MARGIN) {
        esa = vq_exact(row0 + r0, i0a, Z0, cb); eia = i0a;
    }
    if (v1a <= rma + VQ_MARGIN) {
        float s = vq_exact(row0 + r0, i1a, Z0, cb);
        if (s < esa || (s == esa && i1a < eia)) { esa = s; eia = i1a; }
    }
    if (v0b <= rmb + VQ_MARGIN) {
        esb = vq_exact(row0 + r1, i0b, Z1, cb); eib = i0b;
    }
    if (v1b <= rmb + VQ_MARGIN) {
        float s = vq_exact(row0 + r1, i1b, Z1, cb);
        if (s < esb || (s == esb && i1b < eib)) { esb = s; eib = i1b; }
    }
#pragma unroll
    for (int off = 1; off < 4; off <<= 1) {
        float ov = __shfl_xor_sync(0xffffffffu, esa, off);
        int   oi = __shfl_xor_sync(0xffffffffu, eia, off);
        if (ov < esa || (ov == esa && oi < eia)) { esa = ov; eia = oi; }
        ov = __shfl_xor_sync(0xffffffffu, esb, off);
        oi = __shfl_xor_sync(0xffffffffu, eib, off);
        if (ov < esb || (ov == esb && oi < eib)) { esb = ov; eib = oi; }
    }
    if (cg == 0) {
        scode[r0] = eia;
        scode[r1] = eib;
        atomicAdd(&g_counts[eia], 1);
        atomicAdd(&g_counts[eib], 1);
    }
    __syncthreads();

    // gather: write pre-split q (bf16 hi/lo) + squared-error partial
    float lsum = 0.f;
#pragma unroll 4
    for (int it = 0; it < 64; it++) {
        int e = tid + 256 * it;
        int r = e >> 7, d = e & 127;
        int code = scode[r];
        float qv = __ldg(&cb[code * NHID + d]);
        float zv = zrow[e];
        __nv_bfloat16 qh = __float2bfloat16(qv);
        g_qhi[row0 * NHID + e] = qh;
        g_qlo[row0 * NHID + e] = __float2bfloat16(qv - __bfloat162float(qh));
        float df = qv - zv;
        lsum += df * df;
    }
    lred[tid] = lsum;
    __syncthreads();
    for (int s = 128; s > 0; s >>= 1) {
        if (tid < s) lred[tid] += lred[tid + s];
        __syncthreads();
    }
    if (tid == 0) atomicAdd(&g_sse, (double)lred[0]);
}

// ---------------- dec1: convT 128->128, k2, s1, relu -- TENSOR CORES -----
__global__ void __launch_bounds__(256) k_dec1t(const float* __restrict__ bias) {
    __shared__ __align__(16) __nv_bfloat16 Ah[64 * 40];    // [pos][k] +pad
    __shared__ __align__(16) __nv_bfloat16 Al[64 * 40];
    __shared__ __align__(16) __nv_bfloat16 Wh[128 * 40];   // [co][k] +pad
    __shared__ __align__(16) __nv_bfloat16 Wl[128 * 40];
    int b = blockIdx.y;
    int posbase = blockIdx.x * 64;
    int tid = threadIdx.x;
    int warp = tid >> 5, lane = tid & 31;
    int wm = warp >> 1, wn = warp & 1;
    const __nv_bfloat16* qhb = g_qhi + b * (NHID * P2);
    const __nv_bfloat16* qlb = g_qlo + b * (NHID * P2);

    float d[8][4];
#pragma unroll
    for (int i = 0; i < 8; i++)
#pragma unroll
        for (int j = 0; j < 4; j++) d[i][j] = 0.f;

    for (int kb = 0; kb < 512; kb += 32) {
        __syncthreads();
        // A tile: 64 pos x 32 k (im2col of pre-split q)
#pragma unroll
        for (int it = 0; it < 8; it++) {
            int e = tid + 256 * it;             // 2048
            int pl = e & 63, kl = e >> 6;
            int k = kb + kl;
            int ci = k >> 2, kh = (k >> 1) & 1, kw = k & 1;
            int pos = posbase + pl;
            __nv_bfloat16 vh = __float2bfloat16(0.f), vl = vh;
            if (pos < P1) {
                int oh = pos / S1, ow = pos - oh * S1;
                int ih = oh - kh, iw = ow - kw;
                if ((unsigned)ih < (unsigned)S2 && (unsigned)iw < (unsigned)S2) {
                    int idx = ci * P2 + ih * S2 + iw;
                    vh = qhb[idx];
                    vl = qlb[idx];
                }
            }
            Ah[pl * 40 + kl] = vh;
            Al[pl * 40 + kl] = vl;
        }
        // W tile: 128 co x 32 k, vectorized uint4 (8 els/load)
#pragma unroll
        for (int it = 0; it < 2; it++) {
            int u = tid + 256 * it;             // 0..511
            int co = u >> 2, seg = u & 3;
            *(uint4*)&Wh[co * 40 + seg * 8] =
                *(const uint4*)&g_whi[co * 512 + kb + seg * 8];
            *(uint4*)&Wl[co * 40 + seg * 8] =
                *(const uint4*)&g_wlo[co * 512 + kb + seg * 8];
        }
        __syncthreads();
#pragma unroll
        for (int ks = 0; ks < 2; ks++) {
            int k0 = ks * 16;
            int ar = wm * 16 + (lane >> 2);
            int ac = k0 + (lane & 3) * 2;
            uint32_t ah0 = *(const uint32_t*)&Ah[ar * 40 + ac];
            uint32_t ah1 = *(const uint32_t*)&Ah[(ar + 8) * 40 + ac];
            uint32_t ah2 = *(const uint32_t*)&Ah[ar * 40 + ac + 8];
            uint32_t ah3 = *(const uint32_t*)&Ah[(ar + 8) * 40 + ac + 8];
            uint32_t al0 = *(const uint32_t*)&Al[ar * 40 + ac];
            uint32_t al1 = *(const uint32_t*)&Al[(ar + 8) * 40 + ac];
            uint32_t al2 = *(const uint32_t*)&Al[ar * 40 + ac + 8];
            uint32_t al3 = *(const uint32_t*)&Al[(ar + 8) * 40 + ac + 8];
#pragma unroll
            for (int nt = 0; nt < 8; nt++) {
                int co = wn * 64 + nt * 8 + (lane >> 2);
                int kc = k0 + (lane & 3) * 2;
                uint32_t bh0 = *(const uint32_t*)&Wh[co * 40 + kc];
                uint32_t bh1 = *(const uint32_t*)&Wh[co * 40 + kc + 8];
                uint32_t bl0 = *(const uint32_t*)&Wl[co * 40 + kc];
                uint32_t bl1 = *(const uint32_t*)&Wl[co * 40 + kc + 8];
                MMA_BF16(d[nt], ah0, ah1, ah2, ah3, bh0, bh1);   // hi*hi
                MMA_BF16(d[nt], ah0, ah1, ah2, ah3, bl0, bl1);   // hi*lo
                MMA_BF16(d[nt], al0, al1, al2, al3, bh0, bh1);   // lo*hi
            }
        }
    }
    // epilogue: D[pos][co] -> g_y[(b*128+co)*P1 + pos], relu + bias
    int r = lane >> 2, c2 = (lane & 3) * 2;
    int pos0 = posbase + wm * 16 + r;
    int pos1 = pos0 + 8;
#pragma unroll
    for (int nt = 0; nt < 8; nt++) {
        int co0 = wn * 64 + nt * 8 + c2;
        float bi0 = bias[co0], bi1 = bias[co0 + 1];
        float* y0 = g_y + (b * NHID + co0) * P1;
        float* y1 = y0 + P1;
        if (pos0 < P1) {
            y0[pos0] = fmaxf(d[nt][0] + bi0, 0.f);
            y1[pos0] = fmaxf(d[nt][1] + bi1, 0.f);
        }
        if (pos1 < P1) {
            y0[pos1] = fmaxf(d[nt][2] + bi0, 0.f);
            y1[pos1] = fmaxf(d[nt][3] + bi1, 0.f);
        }
    }
}

// ---------------- dec2: convT 128->3, k4, s2 -> x_recon ----------------
extern __shared__ float sm_d2[];
__global__ void __launch_bounds__(192) k_dec2(const float* __restrict__ w,
                                              const float* __restrict__ bias,
                                              float* __restrict__ out) {
    float* sy = sm_d2;           // [2 rows][128 ci][32 iw] = 8192
    float* sw = sm_d2 + 8192;    // full weights 128*3*16 = 6144
    int b = blockIdx.y, t = blockIdx.x;   // outputs oh = 2t, 2t+1
    int tid = threadIdx.x;
    const float* yb = g_y + b * (NHID * P1);

    for (int e = tid; e < 8192; e += 192) {
        int r = e >> 12;
        int rem = e & 4095;
        int ci = rem >> 5, iw = rem & 31;
        int ih = t - r;
        float v = 0.f;
        if (iw < S1 && (unsigned)ih < (unsigned)S1) v = yb[ci * P1 + ih * S1 + iw];
        sy[e] = v;
    }
    for (int e = tid; e < 6144; e += 192) sw[e] = w[e];
    __syncthreads();

    int co = tid >> 6;      // 0..2
    int ow = tid & 63;
    int pw = ow & 1;
    int iw0 = ow >> 1;
    int iw1 = iw0 - 1;
    bool ok1 = (iw1 >= 0);
    int iw1c = ok1 ? iw1 : 0;

    float accE = 0.f, accO = 0.f;
#pragma unroll 4
    for (int ci = 0; ci < NHID; ci++) {
        float y00 = sy[ci * 32 + iw0];
        float y01 = ok1 ? sy[ci * 32 + iw1c] : 0.f;
        float y10 = sy[4096 + ci * 32 + iw0];
        float y11 = ok1 ? sy[4096 + ci * 32 + iw1c] : 0.f;
        const float* wb = sw + ci * 48 + co * 16;
        accE += y00 * wb[pw]      + y01 * wb[pw + 2]
              + y10 * wb[8 + pw]  + y11 * wb[8 + pw + 2];
        accO += y00 * wb[4 + pw]  + y01 * wb[4 + pw + 2]
              + y10 * wb[12 + pw] + y11 * wb[12 + pw + 2];
    }
    float bi = bias[co];
    int base = b * (3 * 4096) + co * 4096 + (2 * t) * 64 + ow;
    out[base]      = accE + bi;
    out[base + 64] = accO + bi;
}

// ---------------- finalize: loss + perplexity ----------------
__global__ void k_final(float* __restrict__ out) {
    __shared__ double sd[1024];
    int t = threadIdx.x;
    double pr = (double)g_counts[t] / (double)NROWS;
    sd[t] = pr * log(pr + 1e-10);
    __syncthreads();
    for (int s = 512; s > 0; s >>= 1) {
        if (t < s) sd[t] += sd[t + s];
        __syncthreads();
    }
    if (t == 0) {
        out[786432] = (float)(1.25 * g_sse / NELEMF);  // loss = (1+beta)*mse
        out[786433] = (float)exp(-sd[0]);              // perplexity
    }
}

// ---------------- launch ----------------
extern "C" void kernel_launch(void* const* d_in, const int* in_sizes, int n_in,
                              void* d_out, int out_size) {
    const float* x   = (const float*)d_in[0];
    const float* ew1 = (const float*)d_in[1];
    const float* eb1 = (const float*)d_in[2];
    const float* ew2 = (const float*)d_in[3];
    const float* eb2 = (const float*)d_in[4];
    const float* cb  = (const float*)d_in[5];
    const float* dw1 = (const float*)d_in[6];
    const float* db1 = (const float*)d_in[7];
    const float* dw2 = (const float*)d_in[8];
    const float* db2 = (const float*)d_in[9];
    float* out = (float*)d_out;

    // k_vqt dynamic smem:
    //   Ah/Al: 2*128*136*2 = 69632 B
    //   Bh/Bl: 2 bufs * 2 arrays * 64*136*2 = 69632 B
    //   cns 4096 + scode 512 + lred 1024
    int vq_smem = 69632 + 69632 + 4096 + 512 + 1024;
    cudaFuncSetAttribute(k_vqt, cudaFuncAttributeMaxDynamicSharedMemorySize,
                         vq_smem);
    cudaFuncSetAttribute(k_dec2, cudaFuncAttributeMaxDynamicSharedMemorySize,
                         (8192 + 6144) * (int)sizeof(float));

    k_prep<<<512, 256>>>(cb, dw1);
    k_conv1<<<dim3(16, NB), 256>>>(x, ew1, eb1);
    k_conv2<<<dim3(15, NB), 256>>>(ew2, eb2);
    k_znorm<<<NROWS / 64, 256>>>();
    k_vqt<<<NROWS / VQ_ROWS, 256, vq_smem>>>(cb);
    k_dec1t<<<dim3(16, NB), 256>>>(db1);
    k_dec2<<<dim3(32, NB), 192, (8192 + 6144) * (int)sizeof(float)>>>(dw2, db2, out);
    k_final<<<1, 1024>>>(out);
}

// round 12
// speedup vs baseline: 1.8449x; 1.0190x over previous
#include <cuda_runtime.h>
#include <cuda_bf16.h>
#include <cstdint>
#include <math.h>

// ---------------- problem constants ----------------
#define NB    64
#define NCIN  3
#define NHID  128
#define NK    1024

#define S1    31          // conv1 out spatial
#define P1    961         // 31*31
#define S2    30          // conv2 out spatial
#define P2    900         // 30*30
#define NROWS 57600       // 64*900 flat VQ rows
#define NELEMF 7372800.0  // 64*128*900

#define VQ_ROWS 128
#define VQ_MARGIN 8e-6f

// ---------------- scratch (device globals; no allocation allowed) ----------
__device__ float  g_z1[NB * NHID * P1];   // encoder conv1 out (relu)
__device__ float  g_z [NB * NHID * P2];   // encoder conv2 out (relu) == flat rows
__device__ float  g_y [NB * NHID * P1];   // dec1 out (relu)
__device__ float  g_cnorm[NK];
__device__ float  g_znorm[NROWS];
__device__ int    g_counts[NK];
__device__ double g_sse;
__device__ __align__(16) __nv_bfloat16 g_whi[NHID * 512];   // dec_w1 hi [co][k]
__device__ __align__(16) __nv_bfloat16 g_wlo[NHID * 512];   // dec_w1 lo
__device__ __align__(16) __nv_bfloat16 g_cbhi[NK * NHID];   // codebook hi [code][d]
__device__ __align__(16) __nv_bfloat16 g_cblo[NK * NHID];
__device__ __align__(16) __nv_bfloat16 g_qhi[NB * NHID * P2];  // quantized split
__device__ __align__(16) __nv_bfloat16 g_qlo[NB * NHID * P2];

// ---------------- helpers ----------------
#define MMA_BF16(d, a0, a1, a2, a3, b0, b1)                                   \
    asm volatile(                                                             \
        "mma.sync.aligned.m16n8k16.row.col.f32.bf16.bf16.f32 "                \
        "{%0,%1,%2,%3}, {%4,%5,%6,%7}, {%8,%9}, {%0,%1,%2,%3};"               \
        : "+f"(d[0]), "+f"(d[1]), "+f"(d[2]), "+f"(d[3])                      \
        : "r"(a0), "r"(a1), "r"(a2), "r"(a3), "r"(b0), "r"(b1))

#define LDSM_X4(r0, r1, r2, r3, a)                                            \
    asm volatile("ldmatrix.sync.aligned.m8n8.x4.shared.b16 {%0,%1,%2,%3}, [%4];" \
        : "=r"(r0), "=r"(r1), "=r"(r2), "=r"(r3) : "r"(a))

#define TOP2(val, idx, v0, v1, i0, i1)                                        \
    if ((val) < (v1)) {                                                       \
        if ((val) < (v0)) { v1 = v0; i1 = i0; v0 = (val); i0 = (idx); }       \
        else              { v1 = (val); i1 = (idx); }                         \
    }

__device__ __forceinline__ uint32_t smaddr(const void* p) {
    return (uint32_t)__cvta_generic_to_shared(p);
}

__device__ __forceinline__ void cp_async16(void* dst, const void* src) {
    unsigned s = (unsigned)__cvta_generic_to_shared(dst);
    asm volatile("cp.async.ca.shared.global [%0], [%1], 16;" :: "r"(s), "l"(src));
}
#define CP_COMMIT asm volatile("cp.async.commit_group;")
#define CP_WAIT1  asm volatile("cp.async.wait_group 1;")
#define CP_WAIT0  asm volatile("cp.async.wait_group 0;")

// ---------------- prep: zero + cnorm + wsplit + cbsplit (one kernel) -----
__global__ void k_prep(const float* __restrict__ cb,
                       const float* __restrict__ dw1) {
    int e = blockIdx.x * 256 + threadIdx.x;   // 131072 threads
    if (e < NK * NHID) {
        float v = cb[e];
        __nv_bfloat16 h = __float2bfloat16(v);
        g_cbhi[e] = h;
        g_cblo[e] = __float2bfloat16(v - __bfloat162float(h));
    }
    if (e < NHID * 512) {
        int co = e >> 9, k = e & 511;
        int ci = k >> 2, tap = k & 3;
        float v = dw1[ci * 512 + co * 4 + tap];
        __nv_bfloat16 h = __float2bfloat16(v);
        g_whi[e] = h;
        g_wlo[e] = __float2bfloat16(v - __bfloat162float(h));
    }
    if (e < NK) {
        g_counts[e] = 0;
        const float* p = cb + e * NHID;
        float s = 0.f;
        for (int d = 0; d < NHID; d++) {
            float m = __fmul_rn(p[d], p[d]);
            s = __fadd_rn(s, m);
        }
        g_cnorm[e] = s;
    }
    if (e == 0) g_sse = 0.0;
}

// ---------------- |z|^2 per flat row: strict sequential ------------------
__global__ void __launch_bounds__(256) k_znorm() {
    __shared__ float s[64 * 129];
    int row0 = blockIdx.x * 64;
    int tid = threadIdx.x;
#pragma unroll
    for (int it = 0; it < 32; it++) {
        int e = tid + 256 * it;
        int r = e >> 7, d = e & 127;
        s[r * 129 + d] = g_z[row0 * NHID + e];
    }
    __syncthreads();
    if (tid < 64) {
        const float* p = s + tid * 129;
        float acc = 0.f;
        for (int d = 0; d < 128; d++) {
            float m = __fmul_rn(p[d], p[d]);
            acc = __fadd_rn(acc, m);
        }
        g_znorm[row0 + tid] = acc;
    }
}

// ---------------- conv1: 3->128, k4, s2, relu (smem GEMM, K=48) ----------
__global__ void __launch_bounds__(256) k_conv1(const float* __restrict__ x,
                                               const float* __restrict__ w,
                                               const float* __restrict__ bias) {
    __shared__ __align__(16) float As[48 * 132];   // [k][co]
    __shared__ __align__(16) float Bs[48 * 68];    // [k][pos]
    int b = blockIdx.y;
    int posbase = blockIdx.x * 64;
    int tid = threadIdx.x, tx = tid & 15, ty = tid >> 4;
    const float* xb = x + b * (NCIN * 64 * 64);

    for (int e = tid; e < 48 * 128; e += 256) {
        int co = e / 48, kl = e - co * 48;
        int kh = kl / 12, r2 = kl - kh * 12;
        int kw = r2 / 3, ci = r2 - kw * 3;
        As[kl * 132 + co] = w[co * 48 + ci * 16 + kh * 4 + kw];
    }
    for (int e = tid; e < 48 * 64; e += 256) {
        int pl = e & 63, kl = e >> 6;
        int kh = kl / 12, r2 = kl - kh * 12;
        int kw = r2 / 3, ci = r2 - kw * 3;
        int pos = posbase + pl;
        float v = 0.f;
        if (pos < P1) {
            int oh = pos / S1, ow = pos - oh * S1;
            v = xb[ci * 4096 + (oh * 2 + kh) * 64 + (ow * 2 + kw)];
        }
        Bs[kl * 68 + pl] = v;
    }
    __syncthreads();

    float acc[8][4];
#pragma unroll
    for (int i = 0; i < 8; i++)
#pragma unroll
        for (int j = 0; j < 4; j++) acc[i][j] = 0.f;

#pragma unroll 8
    for (int kl = 0; kl < 48; kl++) {
        float4 a0 = *(const float4*)(As + kl * 132 + 4 * ty);
        float4 a1 = *(const float4*)(As + kl * 132 + 64 + 4 * ty);
        float4 b0 = *(const float4*)(Bs + kl * 68 + 4 * tx);
        float ar[8] = {a0.x, a0.y, a0.z, a0.w, a1.x, a1.y, a1.z, a1.w};
        float br[4] = {b0.x, b0.y, b0.z, b0.w};
#pragma unroll
        for (int i = 0; i < 8; i++)
#pragma unroll
            for (int j = 0; j < 4; j++)
                acc[i][j] = __fmaf_rn(ar[i], br[j], acc[i][j]);
    }
#pragma unroll
    for (int i = 0; i < 8; i++) {
        int co = (i < 4) ? (4 * ty + i) : (64 + 4 * ty + i - 4);
        float bi = bias[co];
        float* zo = g_z1 + (b * NHID + co) * P1;
#pragma unroll
        for (int j = 0; j < 4; j++) {
            int pos = posbase + 4 * tx + j;
            if (pos < P1) zo[pos] = fmaxf(__fadd_rn(acc[i][j], bi), 0.f);
        }
    }
}

// ---------------- conv2: 128->128, k2, s1, relu (exact fp32 GEMM) --------
__global__ void __launch_bounds__(256) k_conv2(const float* __restrict__ w,
                                               const float* __restrict__ bias) {
    __shared__ __align__(16) float As[32 * 132];   // [k'][co]
    __shared__ __align__(16) float Bs[32 * 68];    // [k'][pos]
    int b = blockIdx.y;
    int posbase = blockIdx.x * 64;
    int tid = threadIdx.x, tx = tid & 15, ty = tid >> 4;
    const float* zin = g_z1 + b * (NHID * P1);

    float acc[8][4];
#pragma unroll
    for (int i = 0; i < 8; i++)
#pragma unroll
        for (int j = 0; j < 4; j++) acc[i][j] = 0.f;

    for (int kb = 0; kb < 512; kb += 32) {
        __syncthreads();
#pragma unroll
        for (int it = 0; it < 16; it++) {            // W tile 32x128
            int e = tid + 256 * it;
            int kl = e & 31, co = e >> 5;
            int kk = kb + kl;
            int ci = kk & 127, tap = kk >> 7;
            As[kl * 132 + co] = w[co * 512 + ci * 4 + tap];
        }
#pragma unroll
        for (int it = 0; it < 8; it++) {             // Im tile 32x64
            int e = tid + 256 * it;
            int pl = e & 63, kl = e >> 6;
            int kk = kb + kl;
            int ci = kk & 127, tap = kk >> 7;
            int kh = tap >> 1, kw = tap & 1;
            int pos = posbase + pl;
            float v = 0.f;
            if (pos < P2) {
                int oh = pos / S2, ow = pos - oh * S2;
                v = zin[ci * P1 + (oh + kh) * S1 + ow + kw];
            }
            Bs[kl * 68 + pl] = v;
        }
        __syncthreads();
#pragma unroll 8
        for (int kl = 0; kl < 32; kl++) {
            float4 a0 = *(const float4*)(As + kl * 132 + 4 * ty);
            float4 a1 = *(const float4*)(As + kl * 132 + 64 + 4 * ty);
            float4 b0 = *(const float4*)(Bs + kl * 68 + 4 * tx);
            float ar[8] = {a0.x, a0.y, a0.z, a0.w, a1.x, a1.y, a1.z, a1.w};
            float br[4] = {b0.x, b0.y, b0.z, b0.w};
#pragma unroll
            for (int i = 0; i < 8; i++)
#pragma unroll
                for (int j = 0; j < 4; j++)
                    acc[i][j] = __fmaf_rn(ar[i], br[j], acc[i][j]);
        }
    }
#pragma unroll
    for (int i = 0; i < 8; i++) {
        int co = (i < 4) ? (4 * ty + i) : (64 + 4 * ty + i - 4);
        float bi = bias[co];
        float* zo = g_z + (b * NHID + co) * P2;
#pragma unroll
        for (int j = 0; j < 4; j++) {
            int pos = posbase + 4 * tx + j;
            if (pos < P2) zo[pos] = fmaxf(__fadd_rn(acc[i][j], bi), 0.f);
        }
    }
}

// ---------------- VQ: tensor-core approx + exact repair ------------------
__device__ __forceinline__ float vq_exact(int grow, int code, float Z,
                                          const float* __restrict__ cb) {
    const float* zp = g_z + grow * NHID;
    const float* cp = cb + code * NHID;
    float acc = 0.f;
    for (int k = 0; k < NHID; k++) acc = __fmaf_rn(zp[k], cp[k], acc);
    float t = __fmaf_rn(-2.0f, acc, Z);
    return __fadd_rn(t, g_cnorm[code]);
}

extern __shared__ unsigned char sm_raw[];
__global__ void __launch_bounds__(256) k_vqt(const float* __restrict__ cb) {
    __nv_bfloat16* Ah = (__nv_bfloat16*)sm_raw;          // [128 rows][136]
    __nv_bfloat16* Al = Ah + 128 * 136;
    __nv_bfloat16* Bh = Al + 128 * 136;                  // [2 bufs][64][136]
    __nv_bfloat16* Bl = Bh + 2 * 64 * 136;
    float* cns   = (float*)(Bl + 2 * 64 * 136);          // 1024
    int*   scode = (int*)(cns + NK);                     // 128
    float* lred  = (float*)(scode + VQ_ROWS);            // 256

    int row0 = blockIdx.x * VQ_ROWS;
    int tid = threadIdx.x, warp = tid >> 5, lane = tid & 31;
    const float* zrow = g_z + row0 * NHID;

    // z tile -> bf16 hi/lo (resident whole kernel; once per block)
#pragma unroll 4
    for (int it = 0; it < 64; it++) {
        int e = tid + 256 * it;        // 16384
        int r = e >> 7, d = e & 127;
        float v = zrow[e];
        __nv_bfloat16 h = __float2bfloat16(v);
        Ah[r * 136 + d] = h;
        Al[r * 136 + d] = __float2bfloat16(v - __bfloat162float(h));
    }
#pragma unroll
    for (int it = 0; it < 4; it++) cns[tid + 256 * it] = g_cnorm[tid + 256 * it];

    int m0 = warp * 16;
    int g = lane >> 2, cg = lane & 3;
    int r0 = m0 + g, r1 = r0 + 8;
    float Z0 = g_znorm[row0 + r0];
    float Z1 = g_znorm[row0 + r1];

    // ldmatrix lane addressing
    int rowA = m0 + ((lane >> 3) & 1) * 8 + (lane & 7);
    int colA = (lane >> 4) * 8;
    uint32_t aHi = smaddr(Ah) + (uint32_t)(rowA * 136 + colA) * 2;
    uint32_t aLo = smaddr(Al) + (uint32_t)(rowA * 136 + colA) * 2;
    int rowB = (lane >> 4) * 8 + (lane & 7);       // 0..15 within pair-tile
    int colB = ((lane >> 3) & 1) * 8;
    uint32_t bOffLane = (uint32_t)(rowB * 136 + colB) * 2;

    float v0a = 3.4e38f, v1a = 3.4e38f; int i0a = 0, i1a = 0;
    float v0b = 3.4e38f, v1b = 3.4e38f; int i0b = 0, i1b = 0;

    // --- codebook chunk copy via cp.async (pre-split bf16 -> smem) ---
#define VQ_ISSUE(c0_, buf_) {                                                  \
        int base_ = (c0_) * NHID;                                              \
        __nv_bfloat16* bhd = Bh + (buf_) * (64 * 136);                         \
        __nv_bfloat16* bld = Bl + (buf_) * (64 * 136);                         \
        _Pragma("unroll")                                                      \
        for (int it = 0; it < 8; it++) {                                       \
            int e = tid + 256 * it;                                            \
            int half = e >> 10, u = e & 1023;                                  \
            int r = u >> 4, seg = u & 15;                                      \
            const __nv_bfloat16* src =                                         \
                (half ? g_cblo : g_cbhi) + base_ + r * NHID + seg * 8;         \
            __nv_bfloat16* dst = (half ? bld : bhd) + r * 136 + seg * 8;       \
            cp_async16(dst, src);                                              \
        }                                                                      \
    }

    VQ_ISSUE(0, 0); CP_COMMIT;

    for (int cc = 0; cc < 16; cc++) {
        int buf = cc & 1;
        int c0 = cc * 64;
        if (cc + 1 < 16) { VQ_ISSUE((cc + 1) * 64, (cc + 1) & 1); CP_COMMIT; CP_WAIT1; }
        else { CP_WAIT0; }
        __syncthreads();

        uint32_t bHiBase = smaddr(Bh + buf * (64 * 136)) + bOffLane;
        uint32_t bLoBase = smaddr(Bl + buf * (64 * 136)) + bOffLane;

        float dacc[8][4];
#pragma unroll
        for (int nt = 0; nt < 8; nt++)
#pragma unroll
            for (int j = 0; j < 4; j++) dacc[nt][j] = 0.f;

#pragma unroll
        for (int ks = 0; ks < 8; ks++) {
            uint32_t ah0, ah1, ah2, ah3, al0, al1, al2, al3;
            LDSM_X4(ah0, ah1, ah2, ah3, aHi + ks * 32);
            LDSM_X4(al0, al1, al2, al3, aLo + ks * 32);
#pragma unroll
            for (int ntp = 0; ntp < 4; ntp++) {
                uint32_t bh0, bh1, bh2, bh3, bl0, bl1, bl2, bl3;
                LDSM_X4(bh0, bh1, bh2, bh3, bHiBase + ntp * (16 * 272) + ks * 32);
                LDSM_X4(bl0, bl1, bl2, bl3, bLoBase + ntp * (16 * 272) + ks * 32);
                MMA_BF16(dacc[2 * ntp],     ah0, ah1, ah2, ah3, bh0, bh1);
                MMA_BF16(dacc[2 * ntp],     ah0, ah1, ah2, ah3, bl0, bl1);
                MMA_BF16(dacc[2 * ntp],     al0, al1, al2, al3, bh0, bh1);
                MMA_BF16(dacc[2 * ntp + 1], ah0, ah1, ah2, ah3, bh2, bh3);
                MMA_BF16(dacc[2 * ntp + 1], ah0, ah1, ah2, ah3, bl2, bl3);
                MMA_BF16(dacc[2 * ntp + 1], al0, al1, al2, al3, bh2, bh3);
            }
        }
#pragma unroll
        for (int nt = 0; nt < 8; nt++) {
            int cA = c0 + nt * 8 + cg * 2;
            float cnA = cns[cA];
            float cnB = cns[cA + 1];
            float s00 = __fmaf_rn(-2.f, dacc[nt][0], Z0) + cnA;
            float s01 = __fmaf_rn(-2.f, dacc[nt][1], Z0) + cnB;
            float s10 = __fmaf_rn(-2.f, dacc[nt][2], Z1) + cnA;
            float s11 = __fmaf_rn(-2.f, dacc[nt][3], Z1) + cnB;
            TOP2(s00, cA,     v0a, v1a, i0a, i1a);
            TOP2(s01, cA + 1, v0a, v1a, i0a, i1a);
            TOP2(s10, cA,     v0b, v1b, i0b, i1b);
            TOP2(s11, cA + 1, v0b, v1b, i0b, i1b);
        }
        __syncthreads();
    }
#undef VQ_ISSUE

    // approx row-min across the 4 lanes sharing each row
    float rma = v0a, rmb = v0b;
#pragma unroll
    for (int off = 1; off < 4; off <<= 1) {
        rma = fminf(rma, __shfl_xor_sync(0xffffffffu, rma, off));
        rmb = fminf(rmb, __shfl_xor_sync(0xffffffffu, rmb, off));
    }

    // candidates -> exact recompute -> lexicographic exact argmin
    float esa = 3.4e38f; int eia = 0x7fffffff;
    float esb = 3.4e38f; int eib = 0x7fffffff;
    if (v0a <= rma + VQ_MARGIN) {
        esa = vq_exact(row0 + r0, i0a, Z0, cb); eia = i0a;
    }
    if (v1a <= rma + VQ_MARGIN) {
        float s = vq_exact(row0 + r0, i1a, Z0, cb);
        if (s < esa || (s == esa && i1a < eia)) { esa = s; eia = i1a; }
    }
    if (v0b <= rmb + VQ_MARGIN) {
        esb = vq_exact(row0 + r1, i0b, Z1, cb); eib = i0b;
    }
    if (v1b <= rmb + VQ_MARGIN) {
        float s = vq_exact(row0 + r1, i1b, Z1, cb);
        if (s < esb || (s == esb && i1b < eib)) { esb = s; eib = i1b; }
    }
#pragma unroll
    for (int off = 1; off < 4; off <<= 1) {
        float ov = __shfl_xor_sync(0xffffffffu, esa, off);
        int   oi = __shfl_xor_sync(0xffffffffu, eia, off);
        if (ov < esa || (ov == esa && oi < eia)) { esa = ov; eia = oi; }
        ov = __shfl_xor_sync(0xffffffffu, esb, off);
        oi = __shfl_xor_sync(0xffffffffu, eib, off);
        if (ov < esb || (ov == esb && oi < eib)) { esb = ov; eib = oi; }
    }
    if (cg == 0) {
        scode[r0] = eia;
        scode[r1] = eib;
        atomicAdd(&g_counts[eia], 1);
        atomicAdd(&g_counts[eib], 1);
    }
    __syncthreads();

    // gather: copy pre-split codebook rows (uint4) + squared-error partial
    float lsum = 0.f;
#pragma unroll
    for (int it = 0; it < 8; it++) {
        int e8 = tid + 256 * it;       // 2048 groups of 8 elems
        int r = e8 >> 4;
        int d0 = (e8 & 15) * 8;
        int code = scode[r];
        int cidx = code * NHID + d0;
        int qidx = (row0 + r) * NHID + d0;
        *(uint4*)&g_qhi[qidx] = *(const uint4*)&g_cbhi[cidx];
        *(uint4*)&g_qlo[qidx] = *(const uint4*)&g_cblo[cidx];
        float4 c0 = *(const float4*)&cb[cidx];
        float4 c1 = *(const float4*)&cb[cidx + 4];
        float4 z0 = *(const float4*)&zrow[r * NHID + d0];
        float4 z1 = *(const float4*)&zrow[r * NHID + d0 + 4];
        float df;
        df = c0.x - z0.x; lsum += df * df;
        df = c0.y - z0.y; lsum += df * df;
        df = c0.z - z0.z; lsum += df * df;
        df = c0.w - z0.w; lsum += df * df;
        df = c1.x - z1.x; lsum += df * df;
        df = c1.y - z1.y; lsum += df * df;
        df = c1.z - z1.z; lsum += df * df;
        df = c1.w - z1.w; lsum += df * df;
    }
    lred[tid] = lsum;
    __syncthreads();
    for (int s = 128; s > 0; s >>= 1) {
        if (tid < s) lred[tid] += lred[tid + s];
        __syncthreads();
    }
    if (tid == 0) atomicAdd(&g_sse, (double)lred[0]);
}

// ---------------- dec1: convT 128->128, k2, s1, relu -- TENSOR CORES -----
__global__ void __launch_bounds__(256) k_dec1t(const float* __restrict__ bias) {
    __shared__ __align__(16) __nv_bfloat16 Ah[64 * 40];    // [pos][k] +pad
    __shared__ __align__(16) __nv_bfloat16 Al[64 * 40];
    __shared__ __align__(16) __nv_bfloat16 Wh[128 * 40];   // [co][k] +pad
    __shared__ __align__(16) __nv_bfloat16 Wl[128 * 40];
    int b = blockIdx.y;
    int posbase = blockIdx.x * 64;
    int tid = threadIdx.x;
    int warp = tid >> 5, lane = tid & 31;
    int wm = warp >> 1, wn = warp & 1;
    const __nv_bfloat16* qhb = g_qhi + b * (NHID * P2);
    const __nv_bfloat16* qlb = g_qlo + b * (NHID * P2);

    // ldmatrix lane addressing (stride 40 elems = 80 B)
    int rowA = wm * 16 + ((lane >> 3) & 1) * 8 + (lane & 7);
    int colA = (lane >> 4) * 8;
    uint32_t aOff = (uint32_t)(rowA * 40 + colA) * 2;
    int rowB = wn * 64 + (lane >> 4) * 8 + (lane & 7);
    int colB = ((lane >> 3) & 1) * 8;
    uint32_t wOff = (uint32_t)(rowB * 40 + colB) * 2;
    uint32_t aHi = smaddr(Ah) + aOff, aLo = smaddr(Al) + aOff;
    uint32_t wHi = smaddr(Wh) + wOff, wLo = smaddr(Wl) + wOff;

    float d[8][4];
#pragma unroll
    for (int i = 0; i < 8; i++)
#pragma unroll
        for (int j = 0; j < 4; j++) d[i][j] = 0.f;

    for (int kb = 0; kb < 512; kb += 32) {
        __syncthreads();
        // A tile: 64 pos x 32 k (im2col of pre-split q)
#pragma unroll
        for (int it = 0; it < 8; it++) {
            int e = tid + 256 * it;             // 2048
            int pl = e & 63, kl = e >> 6;
            int k = kb + kl;
            int ci = k >> 2, kh = (k >> 1) & 1, kw = k & 1;
            int pos = posbase + pl;
            __nv_bfloat16 vh = __float2bfloat16(0.f), vl = vh;
            if (pos < P1) {
                int oh = pos / S1, ow = pos - oh * S1;
                int ih = oh - kh, iw = ow - kw;
                if ((unsigned)ih < (unsigned)S2 && (unsigned)iw < (unsigned)S2) {
                    int idx = ci * P2 + ih * S2 + iw;
                    vh = qhb[idx];
                    vl = qlb[idx];
                }
            }
            Ah[pl * 40 + kl] = vh;
            Al[pl * 40 + kl] = vl;
        }
        // W tile: 128 co x 32 k, vectorized uint4 (8 els/load)
#pragma unroll
        for (int it = 0; it < 2; it++) {
            int u = tid + 256 * it;             // 0..511
            int co = u >> 2, seg = u & 3;
            *(uint4*)&Wh[co * 40 + seg * 8] =
                *(const uint4*)&g_whi[co * 512 + kb + seg * 8];
            *(uint4*)&Wl[co * 40 + seg * 8] =
                *(const uint4*)&g_wlo[co * 512 + kb + seg * 8];
        }
        __syncthreads();
#pragma unroll
        for (int ks = 0; ks < 2; ks++) {
            uint32_t ah0, ah1, ah2, ah3, al0, al1, al2, al3;
            LDSM_X4(ah0, ah1, ah2, ah3, aHi + ks * 32);
            LDSM_X4(al0, al1, al2, al3, aLo + ks * 32);
#pragma unroll
            for (int ntp = 0; ntp < 4; ntp++) {
                uint32_t bh0, bh1, bh2, bh3, bl0, bl1, bl2, bl3;
                LDSM_X4(bh0, bh1, bh2, bh3, wHi + ntp * (16 * 80) + ks * 32);
                LDSM_X4(bl0, bl1, bl2, bl3, wLo + ntp * (16 * 80) + ks * 32);
                MMA_BF16(d[2 * ntp],     ah0, ah1, ah2, ah3, bh0, bh1);
                MMA_BF16(d[2 * ntp],     ah0, ah1, ah2, ah3, bl0, bl1);
                MMA_BF16(d[2 * ntp],     al0, al1, al2, al3, bh0, bh1);
                MMA_BF16(d[2 * ntp + 1], ah0, ah1, ah2, ah3, bh2, bh3);
                MMA_BF16(d[2 * ntp + 1], ah0, ah1, ah2, ah3, bl2, bl3);
                MMA_BF16(d[2 * ntp + 1], al0, al1, al2, al3, bh2, bh3);
            }
        }
    }
    // epilogue: D[pos][co] -> g_y[(b*128+co)*P1 + pos], relu + bias
    int r = lane >> 2, c2 = (lane & 3) * 2;
    int pos0 = posbase + wm * 16 + r;
    int pos1 = pos0 + 8;
#pragma unroll
    for (int nt = 0; nt < 8; nt++) {
        int co0 = wn * 64 + nt * 8 + c2;
        float bi0 = bias[co0], bi1 = bias[co0 + 1];
        float* y0 = g_y + (b * NHID + co0) * P1;
        float* y1 = y0 + P1;
        if (pos0 < P1) {
            y0[pos0] = fmaxf(d[nt][0] + bi0, 0.f);
            y1[pos0] = fmaxf(d[nt][1] + bi1, 0.f);
        }
        if (pos1 < P1) {
            y0[pos1] = fmaxf(d[nt][2] + bi0, 0.f);
            y1[pos1] = fmaxf(d[nt][3] + bi1, 0.f);
        }
    }
}

// ---------------- dec2: convT 128->3, k4, s2 -> x_recon ----------------
extern __shared__ float sm_d2[];
__global__ void __launch_bounds__(192) k_dec2(const float* __restrict__ w,
                                              const float* __restrict__ bias,
                                              float* __restrict__ out) {
    float* sy = sm_d2;           // [2 rows][128 ci][32 iw] = 8192
    float* sw = sm_d2 + 8192;    // full weights 128*3*16 = 6144
    int b = blockIdx.y, t = blockIdx.x;   // outputs oh = 2t, 2t+1
    int tid = threadIdx.x;
    const float* yb = g_y + b * (NHID * P1);

    for (int e = tid; e < 8192; e += 192) {
        int r = e >> 12;
        int rem = e & 4095;
        int ci = rem >> 5, iw = rem & 31;
        int ih = t - r;
        float v = 0.f;
        if (iw < S1 && (unsigned)ih < (unsigned)S1) v = yb[ci * P1 + ih * S1 + iw];
        sy[e] = v;
    }
    for (int e = tid; e < 6144; e += 192) sw[e] = w[e];
    __syncthreads();

    int co = tid >> 6;      // 0..2
    int ow = tid & 63;
    int pw = ow & 1;
    int iw0 = ow >> 1;
    int iw1 = iw0 - 1;
    bool ok1 = (iw1 >= 0);
    int iw1c = ok1 ? iw1 : 0;

    float accE = 0.f, accO = 0.f;
#pragma unroll 4
    for (int ci = 0; ci < NHID; ci++) {
        float y00 = sy[ci * 32 + iw0];
        float y01 = ok1 ? sy[ci * 32 + iw1c] : 0.f;
        float y10 = sy[4096 + ci * 32 + iw0];
        float y11 = ok1 ? sy[4096 + ci * 32 + iw1c] : 0.f;
        const float* wb = sw + ci * 48 + co * 16;
        accE += y00 * wb[pw]      + y01 * wb[pw + 2]
              + y10 * wb[8 + pw]  + y11 * wb[8 + pw + 2];
        accO += y00 * wb[4 + pw]  + y01 * wb[4 + pw + 2]
              + y10 * wb[12 + pw] + y11 * wb[12 + pw + 2];
    }
    float bi = bias[co];
    int base = b * (3 * 4096) + co * 4096 + (2 * t) * 64 + ow;
    out[base]      = accE + bi;
    out[base + 64] = accO + bi;
}

// ---------------- finalize: loss + perplexity ----------------
__global__ void k_final(float* __restrict__ out) {
    __shared__ double sd[1024];
    int t = threadIdx.x;
    double pr = (double)g_counts[t] / (double)NROWS;
    sd[t] = pr * log(pr + 1e-10);
    __syncthreads();
    for (int s = 512; s > 0; s >>= 1) {
        if (t < s) sd[t] += sd[t + s];
        __syncthreads();
    }
    if (t == 0) {
        out[786432] = (float)(1.25 * g_sse / NELEMF);  // loss = (1+beta)*mse
        out[786433] = (float)exp(-sd[0]);              // perplexity
    }
}

// ---------------- launch ----------------
extern "C" void kernel_launch(void* const* d_in, const int* in_sizes, int n_in,
                              void* d_out, int out_size) {
    const float* x   = (const float*)d_in[0];
    const float* ew1 = (const float*)d_in[1];
    const float* eb1 = (const float*)d_in[2];
    const float* ew2 = (const float*)d_in[3];
    const float* eb2 = (const float*)d_in[4];
    const float* cb  = (const float*)d_in[5];
    const float* dw1 = (const float*)d_in[6];
    const float* db1 = (const float*)d_in[7];
    const float* dw2 = (const float*)d_in[8];
    const float* db2 = (const float*)d_in[9];
    float* out = (float*)d_out;

    int vq_smem = 69632 + 69632 + 4096 + 512 + 1024;
    cudaFuncSetAttribute(k_vqt, cudaFuncAttributeMaxDynamicSharedMemorySize,
                         vq_smem);
    cudaFuncSetAttribute(k_dec2, cudaFuncAttributeMaxDynamicSharedMemorySize,
                         (8192 + 6144) * (int)sizeof(float));

    k_prep<<<512, 256>>>(cb, dw1);
    k_conv1<<<dim3(16, NB), 256>>>(x, ew1, eb1);
    k_conv2<<<dim3(15, NB), 256>>>(ew2, eb2);
    k_znorm<<<NROWS / 64, 256>>>();
    k_vqt<<<NROWS / VQ_ROWS, 256, vq_smem>>>(cb);
    k_dec1t<<<dim3(16, NB), 256>>>(db1);
    k_dec2<<<dim3(32, NB), 192, (8192 + 6144) * (int)sizeof(float)>>>(dw2, db2, out);
    k_final<<<1, 1024>>>(out);
}

// round 14
// speedup vs baseline: 2.0361x; 1.1036x over previous
#include <cuda_runtime.h>
#include <cuda_bf16.h>
#include <cstdint>
#include <math.h>

// ---------------- problem constants ----------------
#define NB    64
#define NCIN  3
#define NHID  128
#define NK    1024

#define S1    31          // conv1 out spatial
#define P1    961         // 31*31
#define S2    30          // conv2 out spatial
#define P2    900         // 30*30
#define NROWS 57600       // 64*900 flat VQ rows
#define NELEMF 7372800.0  // 64*128*900

#define VQ_ROWS 128
#define VQ_MARGIN 6e-5f

// ---------------- scratch (device globals; no allocation allowed) ----------
__device__ float  g_z1[NB * NHID * P1];   // encoder conv1 out (relu)
__device__ float  g_z [NB * NHID * P2];   // encoder conv2 out (relu) == flat rows
__device__ float  g_y [NB * NHID * P1];   // dec1 out (relu)
__device__ float  g_cnorm[NK];
__device__ float  g_znorm[NROWS];
__device__ int    g_counts[NK];
__device__ double g_sse;
__device__ __align__(16) __nv_bfloat16 g_whi[NHID * 512];   // dec_w1 hi [co][k]
__device__ __align__(16) __nv_bfloat16 g_wlo[NHID * 512];   // dec_w1 lo
__device__ __align__(16) __nv_bfloat16 g_cbhi[NK * NHID];   // codebook hi [code][d]
__device__ __align__(16) __nv_bfloat16 g_cblo[NK * NHID];
__device__ __align__(16) __nv_bfloat16 g_qhi[NB * NHID * P2];  // quantized split
__device__ __align__(16) __nv_bfloat16 g_qlo[NB * NHID * P2];

// ---------------- helpers ----------------
#define MMA_BF16(d, a0, a1, a2, a3, b0, b1)                                   \
    asm volatile(                                                             \
        "mma.sync.aligned.m16n8k16.row.col.f32.bf16.bf16.f32 "                \
        "{%0,%1,%2,%3}, {%4,%5,%6,%7}, {%8,%9}, {%0,%1,%2,%3};"               \
        : "+f"(d[0]), "+f"(d[1]), "+f"(d[2]), "+f"(d[3])                      \
        : "r"(a0), "r"(a1), "r"(a2), "r"(a3), "r"(b0), "r"(b1))

#define LDSM_X4(r0, r1, r2, r3, a)                                            \
    asm volatile("ldmatrix.sync.aligned.m8n8.x4.shared.b16 {%0,%1,%2,%3}, [%4];" \
        : "=r"(r0), "=r"(r1), "=r"(r2), "=r"(r3) : "r"(a))

#define TOP3(val, idx, v0, v1, v2, i0, i1, i2)                                \
    if ((val) < (v2)) {                                                       \
        if ((val) < (v1)) {                                                   \
            if ((val) < (v0)) { v2 = v1; i2 = i1; v1 = v0; i1 = i0;           \
                                v0 = (val); i0 = (idx); }                     \
            else { v2 = v1; i2 = i1; v1 = (val); i1 = (idx); }                \
        } else { v2 = (val); i2 = (idx); }                                    \
    }

__device__ __forceinline__ uint32_t smaddr(const void* p) {
    return (uint32_t)__cvta_generic_to_shared(p);
}

__device__ __forceinline__ void cp_async16(void* dst, const void* src) {
    unsigned s = (unsigned)__cvta_generic_to_shared(dst);
    asm volatile("cp.async.ca.shared.global [%0], [%1], 16;" :: "r"(s), "l"(src));
}
#define CP_COMMIT asm volatile("cp.async.commit_group;")
#define CP_WAIT1  asm volatile("cp.async.wait_group 1;")
#define CP_WAIT0  asm volatile("cp.async.wait_group 0;")

// ---------------- prep: zero + cnorm + wsplit + cbsplit (one kernel) -----
__global__ void k_prep(const float* __restrict__ cb,
                       const float* __restrict__ dw1) {
    int e = blockIdx.x * 256 + threadIdx.x;   // 131072 threads
    if (e < NK * NHID) {
        float v = cb[e];
        __nv_bfloat16 h = __float2bfloat16(v);
        g_cbhi[e] = h;
        g_cblo[e] = __float2bfloat16(v - __bfloat162float(h));
    }
    if (e < NHID * 512) {
        int co = e >> 9, k = e & 511;
        int ci = k >> 2, tap = k & 3;
        float v = dw1[ci * 512 + co * 4 + tap];
        __nv_bfloat16 h = __float2bfloat16(v);
        g_whi[e] = h;
        g_wlo[e] = __float2bfloat16(v - __bfloat162float(h));
    }
    if (e < NK) {
        g_counts[e] = 0;
        const float* p = cb + e * NHID;
        float s = 0.f;
        for (int d = 0; d < NHID; d++) {
            float m = __fmul_rn(p[d], p[d]);
            s = __fadd_rn(s, m);
        }
        g_cnorm[e] = s;
    }
    if (e == 0) g_sse = 0.0;
}

// ---------------- |z|^2 per flat row: strict sequential ------------------
__global__ void __launch_bounds__(256) k_znorm() {
    __shared__ float s[64 * 129];
    int row0 = blockIdx.x * 64;
    int tid = threadIdx.x;
#pragma unroll
    for (int it = 0; it < 32; it++) {
        int e = tid + 256 * it;
        int r = e >> 7, d = e & 127;
        s[r * 129 + d] = g_z[row0 * NHID + e];
    }
    __syncthreads();
    if (tid < 64) {
        const float* p = s + tid * 129;
        float acc = 0.f;
        for (int d = 0; d < 128; d++) {
            float m = __fmul_rn(p[d], p[d]);
            acc = __fadd_rn(acc, m);
        }
        g_znorm[row0 + tid] = acc;
    }
}

// ---------------- conv1: 3->128, k4, s2, relu (smem GEMM, K=48) ----------
__global__ void __launch_bounds__(256) k_conv1(const float* __restrict__ x,
                                               const float* __restrict__ w,
                                               const float* __restrict__ bias) {
    __shared__ __align__(16) float As[48 * 132];   // [k][co]
    __shared__ __align__(16) float Bs[48 * 68];    // [k][pos]
    int b = blockIdx.y;
    int posbase = blockIdx.x * 64;
    int tid = threadIdx.x, tx = tid & 15, ty = tid >> 4;
    const float* xb = x + b * (NCIN * 64 * 64);

    for (int e = tid; e < 48 * 128; e += 256) {
        int co = e / 48, kl = e - co * 48;
        int kh = kl / 12, r2 = kl - kh * 12;
        int kw = r2 / 3, ci = r2 - kw * 3;
        As[kl * 132 + co] = w[co * 48 + ci * 16 + kh * 4 + kw];
    }
    for (int e = tid; e < 48 * 64; e += 256) {
        int pl = e & 63, kl = e >> 6;
        int kh = kl / 12, r2 = kl - kh * 12;
        int kw = r2 / 3, ci = r2 - kw * 3;
        int pos = posbase + pl;
        float v = 0.f;
        if (pos < P1) {
            int oh = pos / S1, ow = pos - oh * S1;
            v = xb[ci * 4096 + (oh * 2 + kh) * 64 + (ow * 2 + kw)];
        }
        Bs[kl * 68 + pl] = v;
    }
    __syncthreads();

    float acc[8][4];
#pragma unroll
    for (int i = 0; i < 8; i++)
#pragma unroll
        for (int j = 0; j < 4; j++) acc[i][j] = 0.f;

#pragma unroll 8
    for (int kl = 0; kl < 48; kl++) {
        float4 a0 = *(const float4*)(As + kl * 132 + 4 * ty);
        float4 a1 = *(const float4*)(As + kl * 132 + 64 + 4 * ty);
        float4 b0 = *(const float4*)(Bs + kl * 68 + 4 * tx);
        float ar[8] = {a0.x, a0.y, a0.z, a0.w, a1.x, a1.y, a1.z, a1.w};
        float br[4] = {b0.x, b0.y, b0.z, b0.w};
#pragma unroll
        for (int i = 0; i < 8; i++)
#pragma unroll
            for (int j = 0; j < 4; j++)
                acc[i][j] = __fmaf_rn(ar[i], br[j], acc[i][j]);
    }
#pragma unroll
    for (int i = 0; i < 8; i++) {
        int co = (i < 4) ? (4 * ty + i) : (64 + 4 * ty + i - 4);
        float bi = bias[co];
        float* zo = g_z1 + (b * NHID + co) * P1;
#pragma unroll
        for (int j = 0; j < 4; j++) {
            int pos = posbase + 4 * tx + j;
            if (pos < P1) zo[pos] = fmaxf(__fadd_rn(acc[i][j], bi), 0.f);
        }
    }
}

// ---------------- conv2: 128->128, k2, s1, relu (exact fp32 GEMM) --------
__global__ void __launch_bounds__(256) k_conv2(const float* __restrict__ w,
                                               const float* __restrict__ bias) {
    __shared__ __align__(16) float As[32 * 132];   // [k'][co]
    __shared__ __align__(16) float Bs[32 * 68];    // [k'][pos]
    int b = blockIdx.y;
    int posbase = blockIdx.x * 64;
    int tid = threadIdx.x, tx = tid & 15, ty = tid >> 4;
    const float* zin = g_z1 + b * (NHID * P1);

    float acc[8][4];
#pragma unroll
    for (int i = 0; i < 8; i++)
#pragma unroll
        for (int j = 0; j < 4; j++) acc[i][j] = 0.f;

    for (int kb = 0; kb < 512; kb += 32) {
        __syncthreads();
#pragma unroll
        for (int it = 0; it < 16; it++) {            // W tile 32x128
            int e = tid + 256 * it;
            int kl = e & 31, co = e >> 5;
            int kk = kb + kl;
            int ci = kk & 127, tap = kk >> 7;
            As[kl * 132 + co] = w[co * 512 + ci * 4 + tap];
        }
#pragma unroll
        for (int it = 0; it < 8; it++) {             // Im tile 32x64
            int e = tid + 256 * it;
            int pl = e & 63, kl = e >> 6;
            int kk = kb + kl;
            int ci = kk & 127, tap = kk >> 7;
            int kh = tap >> 1, kw = tap & 1;
            int pos = posbase + pl;
            float v = 0.f;
            if (pos < P2) {
                int oh = pos / S2, ow = pos - oh * S2;
                v = zin[ci * P1 + (oh + kh) * S1 + ow + kw];
            }
            Bs[kl * 68 + pl] = v;
        }
        __syncthreads();
#pragma unroll 8
        for (int kl = 0; kl < 32; kl++) {
            float4 a0 = *(const float4*)(As + kl * 132 + 4 * ty);
            float4 a1 = *(const float4*)(As + kl * 132 + 64 + 4 * ty);
            float4 b0 = *(const float4*)(Bs + kl * 68 + 4 * tx);
            float ar[8] = {a0.x, a0.y, a0.z, a0.w, a1.x, a1.y, a1.z, a1.w};
            float br[4] = {b0.x, b0.y, b0.z, b0.w};
#pragma unroll
            for (int i = 0; i < 8; i++)
#pragma unroll
                for (int j = 0; j < 4; j++)
                    acc[i][j] = __fmaf_rn(ar[i], br[j], acc[i][j]);
        }
    }
#pragma unroll
    for (int i = 0; i < 8; i++) {
        int co = (i < 4) ? (4 * ty + i) : (64 + 4 * ty + i - 4);
        float bi = bias[co];
        float* zo = g_z + (b * NHID + co) * P2;
#pragma unroll
        for (int j = 0; j < 4; j++) {
            int pos = posbase + 4 * tx + j;
            if (pos < P2) zo[pos] = fmaxf(__fadd_rn(acc[i][j], bi), 0.f);
        }
    }
}

// ---------------- VQ: 1-product bf16 screen + exact repair ---------------
__device__ __forceinline__ float vq_exact(int grow, int code, float Z,
                                          const float* __restrict__ cb) {
    const float* zp = g_z + grow * NHID;
    const float* cp = cb + code * NHID;
    float acc = 0.f;
    for (int k = 0; k < NHID; k++) acc = __fmaf_rn(zp[k], cp[k], acc);
    float t = __fmaf_rn(-2.0f, acc, Z);
    return __fadd_rn(t, g_cnorm[code]);
}

// lexicographic-min repair of a lane's tracked entry
__device__ __forceinline__ void vq_repair(float v, int i, float rm, int grow,
                                          float Z, const float* cb,
                                          float& es, int& ei) {
    if (v <= rm + VQ_MARGIN) {
        float s = vq_exact(grow, i, Z, cb);
        if (s < es || (s == es && i < ei)) { es = s; ei = i; }
    }
}

extern __shared__ unsigned char sm_raw[];
__global__ void __launch_bounds__(256) k_vqt(const float* __restrict__ cb) {
    __nv_bfloat16* Ah = (__nv_bfloat16*)sm_raw;          // [128 rows][136]
    __nv_bfloat16* Bh = Ah + 128 * 136;                  // [2 bufs][64][136]
    float* cns   = (float*)(Bh + 2 * 64 * 136);          // 1024
    int*   scode = (int*)(cns + NK);                     // 128
    float* lred  = (float*)(scode + VQ_ROWS);            // 256

    int row0 = blockIdx.x * VQ_ROWS;
    int tid = threadIdx.x, warp = tid >> 5, lane = tid & 31;
    const float* zrow = g_z + row0 * NHID;

    // z tile -> bf16 hi (resident whole kernel; once per block)
#pragma unroll 4
    for (int it = 0; it < 64; it++) {
        int e = tid + 256 * it;        // 16384
        int r = e >> 7, d = e & 127;
        Ah[r * 136 + d] = __float2bfloat16(zrow[e]);
    }
#pragma unroll
    for (int it = 0; it < 4; it++) cns[tid + 256 * it] = g_cnorm[tid + 256 * it];

    int m0 = warp * 16;
    int g = lane >> 2, cg = lane & 3;
    int r0 = m0 + g, r1 = r0 + 8;
    float Z0 = g_znorm[row0 + r0];
    float Z1 = g_znorm[row0 + r1];

    // ldmatrix lane addressing
    int rowA = m0 + ((lane >> 3) & 1) * 8 + (lane & 7);
    int colA = (lane >> 4) * 8;
    uint32_t aHi = smaddr(Ah) + (uint32_t)(rowA * 136 + colA) * 2;
    int rowB = (lane >> 4) * 8 + (lane & 7);       // 0..15 within pair-tile
    int colB = ((lane >> 3) & 1) * 8;
    uint32_t bOffLane = (uint32_t)(rowB * 136 + colB) * 2;

    float v0a = 3.4e38f, v1a = 3.4e38f, v2a = 3.4e38f;
    int   i0a = 0, i1a = 0, i2a = 0;
    float v0b = 3.4e38f, v1b = 3.4e38f, v2b = 3.4e38f;
    int   i0b = 0, i1b = 0, i2b = 0;

    // codebook chunk copy via cp.async (hi only): 1024 x 16B per chunk
#define VQ_ISSUE(c0_, buf_) {                                                  \
        int base_ = (c0_) * NHID;                                              \
        __nv_bfloat16* bhd = Bh + (buf_) * (64 * 136);                         \
        _Pragma("unroll")                                                      \
        for (int it = 0; it < 4; it++) {                                       \
            int e = tid + 256 * it;                                            \
            int r = e >> 4, seg = e & 15;                                      \
            cp_async16(bhd + r * 136 + seg * 8,                                \
                       g_cbhi + base_ + r * NHID + seg * 8);                   \
        }                                                                      \
    }

    VQ_ISSUE(0, 0); CP_COMMIT;

    for (int cc = 0; cc < 16; cc++) {
        int buf = cc & 1;
        int c0 = cc * 64;
        if (cc + 1 < 16) { VQ_ISSUE((cc + 1) * 64, (cc + 1) & 1); CP_COMMIT; CP_WAIT1; }
        else { CP_WAIT0; }
        __syncthreads();

        uint32_t bHiBase = smaddr(Bh + buf * (64 * 136)) + bOffLane;

        float dacc[8][4];
#pragma unroll
        for (int nt = 0; nt < 8; nt++)
#pragma unroll
            for (int j = 0; j < 4; j++) dacc[nt][j] = 0.f;

#pragma unroll
        for (int ks = 0; ks < 8; ks++) {
            uint32_t ah0, ah1, ah2, ah3;
            LDSM_X4(ah0, ah1, ah2, ah3, aHi + ks * 32);
#pragma unroll
            for (int ntp = 0; ntp < 4; ntp++) {
                uint32_t bh0, bh1, bh2, bh3;
                LDSM_X4(bh0, bh1, bh2, bh3, bHiBase + ntp * (16 * 272) + ks * 32);
                MMA_BF16(dacc[2 * ntp],     ah0, ah1, ah2, ah3, bh0, bh1);
                MMA_BF16(dacc[2 * ntp + 1], ah0, ah1, ah2, ah3, bh2, bh3);
            }
        }
#pragma unroll
        for (int nt = 0; nt < 8; nt++) {
            int cA = c0 + nt * 8 + cg * 2;
            float cnA = cns[cA];
            float cnB = cns[cA + 1];
            float s00 = __fmaf_rn(-2.f, dacc[nt][0], Z0) + cnA;
            float s01 = __fmaf_rn(-2.f, dacc[nt][1], Z0) + cnB;
            float s10 = __fmaf_rn(-2.f, dacc[nt][2], Z1) + cnA;
            float s11 = __fmaf_rn(-2.f, dacc[nt][3], Z1) + cnB;
            TOP3(s00, cA,     v0a, v1a, v2a, i0a, i1a, i2a);
            TOP3(s01, cA + 1, v0a, v1a, v2a, i0a, i1a, i2a);
            TOP3(s10, cA,     v0b, v1b, v2b, i0b, i1b, i2b);
            TOP3(s11, cA + 1, v0b, v1b, v2b, i0b, i1b, i2b);
        }
        __syncthreads();
    }
#undef VQ_ISSUE

    // approx row-min across the 4 lanes sharing each row
    float rma = v0a, rmb = v0b;
#pragma unroll
    for (int off = 1; off < 4; off <<= 1) {
        rma = fminf(rma, __shfl_xor_sync(0xffffffffu, rma, off));
        rmb = fminf(rmb, __shfl_xor_sync(0xffffffffu, rmb, off));
    }

    // candidates (top-3/lane within margin) -> exact recompute
    float esa = 3.4e38f; int eia = 0x7fffffff;
    float esb = 3.4e38f; int eib = 0x7fffffff;
    vq_repair(v0a, i0a, rma, row0 + r0, Z0, cb, esa, eia);
    vq_repair(v1a, i1a, rma, row0 + r0, Z0, cb, esa, eia);
    vq_repair(v2a, i2a, rma, row0 + r0, Z0, cb, esa, eia);
    vq_repair(v0b, i0b, rmb, row0 + r1, Z1, cb, esb, eib);
    vq_repair(v1b, i1b, rmb, row0 + r1, Z1, cb, esb, eib);
    vq_repair(v2b, i2b, rmb, row0 + r1, Z1, cb, esb, eib);
#pragma unroll
    for (int off = 1; off < 4; off <<= 1) {
        float ov = __shfl_xor_sync(0xffffffffu, esa, off);
        int   oi = __shfl_xor_sync(0xffffffffu, eia, off);
        if (ov < esa || (ov == esa && oi < eia)) { esa = ov; eia = oi; }
        ov = __shfl_xor_sync(0xffffffffu, esb, off);
        oi = __shfl_xor_sync(0xffffffffu, eib, off);
        if (ov < esb || (ov == esb && oi < eib)) { esb = ov; eib = oi; }
    }
    if (cg == 0) {
        scode[r0] = eia;
        scode[r1] = eib;
        atomicAdd(&g_counts[eia], 1);
        atomicAdd(&g_counts[eib], 1);
    }
    __syncthreads();

    // gather: copy pre-split codebook rows (uint4) + squared-error partial
    float lsum = 0.f;
#pragma unroll
    for (int it = 0; it < 8; it++) {
        int e8 = tid + 256 * it;       // 2048 groups of 8 elems
        int r = e8 >> 4;
        int d0 = (e8 & 15) * 8;
        int code = scode[r];
        int cidx = code * NHID + d0;
        int qidx = (row0 + r) * NHID + d0;
        *(uint4*)&g_qhi[qidx] = *(const uint4*)&g_cbhi[cidx];
        *(uint4*)&g_qlo[qidx] = *(const uint4*)&g_cblo[cidx];
        float4 c0 = *(const float4*)&cb[cidx];
        float4 c1 = *(const float4*)&cb[cidx + 4];
        float4 z0 = *(const float4*)&zrow[r * NHID + d0];
        float4 z1 = *(const float4*)&zrow[r * NHID + d0 + 4];
        float df;
        df = c0.x - z0.x; lsum += df * df;
        df = c0.y - z0.y; lsum += df * df;
        df = c0.z - z0.z; lsum += df * df;
        df = c0.w - z0.w; lsum += df * df;
        df = c1.x - z1.x; lsum += df * df;
        df = c1.y - z1.y; lsum += df * df;
        df = c1.z - z1.z; lsum += df * df;
        df = c1.w - z1.w; lsum += df * df;
    }
    lred[tid] = lsum;
    __syncthreads();
    for (int s = 128; s > 0; s >>= 1) {
        if (tid < s) lred[tid] += lred[tid + s];
        __syncthreads();
    }
    if (tid == 0) atomicAdd(&g_sse, (double)lred[0]);
}

// ---------------- dec1: convT 128->128, k2, s1, relu -- TENSOR CORES -----
// stays 3-product: q is small (|q|<1/1024) so q_lo genuinely matters
__global__ void __launch_bounds__(256) k_dec1t(const float* __restrict__ bias) {
    __shared__ __align__(16) __nv_bfloat16 Ah[64 * 40];    // [pos][k] +pad
    __shared__ __align__(16) __nv_bfloat16 Al[64 * 40];
    __shared__ __align__(16) __nv_bfloat16 Wh[128 * 40];   // [co][k] +pad
    __shared__ __align__(16) __nv_bfloat16 Wl[128 * 40];
    int b = blockIdx.y;
    int posbase = blockIdx.x * 64;
    int tid = threadIdx.x;
    int warp = tid >> 5, lane = tid & 31;
    int wm = warp >> 1, wn = warp & 1;
    const __nv_bfloat16* qhb = g_qhi + b * (NHID * P2);
    const __nv_bfloat16* qlb = g_qlo + b * (NHID * P2);

    int rowA = wm * 16 + ((lane >> 3) & 1) * 8 + (lane & 7);
    int colA = (lane >> 4) * 8;
    uint32_t aOff = (uint32_t)(rowA * 40 + colA) * 2;
    int rowB = wn * 64 + (lane >> 4) * 8 + (lane & 7);
    int colB = ((lane >> 3) & 1) * 8;
    uint32_t wOff = (uint32_t)(rowB * 40 + colB) * 2;
    uint32_t aHi = smaddr(Ah) + aOff, aLo = smaddr(Al) + aOff;
    uint32_t wHi = smaddr(Wh) + wOff, wLo = smaddr(Wl) + wOff;

    float d[8][4];
#pragma unroll
    for (int i = 0; i < 8; i++)
#pragma unroll
        for (int j = 0; j < 4; j++) d[i][j] = 0.f;

    for (int kb = 0; kb < 512; kb += 32) {
        __syncthreads();
#pragma unroll
        for (int it = 0; it < 8; it++) {
            int e = tid + 256 * it;             // 2048
            int pl = e & 63, kl = e >> 6;
            int k = kb + kl;
            int ci = k >> 2, kh = (k >> 1) & 1, kw = k & 1;
            int pos = posbase + pl;
            __nv_bfloat16 vh = __float2bfloat16(0.f), vl = vh;
            if (pos < P1) {
                int oh = pos / S1, ow = pos - oh * S1;
                int ih = oh - kh, iw = ow - kw;
                if ((unsigned)ih < (unsigned)S2 && (unsigned)iw < (unsigned)S2) {
                    int idx = ci * P2 + ih * S2 + iw;
                    vh = qhb[idx];
                    vl = qlb[idx];
                }
            }
            Ah[pl * 40 + kl] = vh;
            Al[pl * 40 + kl] = vl;
        }
#pragma unroll
        for (int it = 0; it < 2; it++) {
            int u = tid + 256 * it;             // 0..511
            int co = u >> 2, seg = u & 3;
            *(uint4*)&Wh[co * 40 + seg * 8] =
                *(const uint4*)&g_whi[co * 512 + kb + seg * 8];
            *(uint4*)&Wl[co * 40 + seg * 8] =
                *(const uint4*)&g_wlo[co * 512 + kb + seg * 8];
        }
        __syncthreads();
#pragma unroll
        for (int ks = 0; ks < 2; ks++) {
            uint32_t ah0, ah1, ah2, ah3, al0, al1, al2, al3;
            LDSM_X4(ah0, ah1, ah2, ah3, aHi + ks * 32);
            LDSM_X4(al0, al1, al2, al3, aLo + ks * 32);
#pragma unroll
            for (int ntp = 0; ntp < 4; ntp++) {
                uint32_t bh0, bh1, bh2, bh3, bl0, bl1, bl2, bl3;
                LDSM_X4(bh0, bh1, bh2, bh3, wHi + ntp * (16 * 80) + ks * 32);
                LDSM_X4(bl0, bl1, bl2, bl3, wLo + ntp * (16 * 80) + ks * 32);
                MMA_BF16(d[2 * ntp],     ah0, ah1, ah2, ah3, bh0, bh1);
                MMA_BF16(d[2 * ntp],     ah0, ah1, ah2, ah3, bl0, bl1);
                MMA_BF16(d[2 * ntp],     al0, al1, al2, al3, bh0, bh1);
                MMA_BF16(d[2 * ntp + 1], ah0, ah1, ah2, ah3, bh2, bh3);
                MMA_BF16(d[2 * ntp + 1], ah0, ah1, ah2, ah3, bl2, bl3);
                MMA_BF16(d[2 * ntp + 1], al0, al1, al2, al3, bh2, bh3);
            }
        }
    }
    int r = lane >> 2, c2 = (lane & 3) * 2;
    int pos0 = posbase + wm * 16 + r;
    int pos1 = pos0 + 8;
#pragma unroll
    for (int nt = 0; nt < 8; nt++) {
        int co0 = wn * 64 + nt * 8 + c2;
        float bi0 = bias[co0], bi1 = bias[co0 + 1];
        float* y0 = g_y + (b * NHID + co0) * P1;
        float* y1 = y0 + P1;
        if (pos0 < P1) {
            y0[pos0] = fmaxf(d[nt][0] + bi0, 0.f);
            y1[pos0] = fmaxf(d[nt][1] + bi1, 0.f);
        }
        if (pos1 < P1) {
            y0[pos1] = fmaxf(d[nt][2] + bi0, 0.f);
            y1[pos1] = fmaxf(d[nt][3] + bi1, 0.f);
        }
    }
}

// ---------------- dec2: convT 128->3, k4, s2 -> x_recon ----------------
extern __shared__ float sm_d2[];
__global__ void __launch_bounds__(192) k_dec2(const float* __restrict__ w,
                                              const float* __restrict__ bias,
                                              float* __restrict__ out) {
    float* sy = sm_d2;           // [2 rows][128 ci][32 iw] = 8192
    float* sw = sm_d2 + 8192;    // full weights 128*3*16 = 6144
    int b = blockIdx.y, t = blockIdx.x;   // outputs oh = 2t, 2t+1
    int tid = threadIdx.x;
    const float* yb = g_y + b * (NHID * P1);

    for (int e = tid; e < 8192; e += 192) {
        int r = e >> 12;
        int rem = e & 4095;
        int ci = rem >> 5, iw = rem & 31;
        int ih = t - r;
        float v = 0.f;
        if (iw < S1 && (unsigned)ih < (unsigned)S1) v = yb[ci * P1 + ih * S1 + iw];
        sy[e] = v;
    }
    for (int e = tid; e < 6144; e += 192) sw[e] = w[e];
    __syncthreads();

    int co = tid >> 6;      // 0..2
    int ow = tid & 63;
    int pw = ow & 1;
    int iw0 = ow >> 1;
    int iw1 = iw0 - 1;
    bool ok1 = (iw1 >= 0);
    int iw1c = ok1 ? iw1 : 0;

    float accE = 0.f, accO = 0.f;
#pragma unroll 4
    for (int ci = 0; ci < NHID; ci++) {
        float y00 = sy[ci * 32 + iw0];
        float y01 = ok1 ? sy[ci * 32 + iw1c] : 0.f;
        float y10 = sy[4096 + ci * 32 + iw0];
        float y11 = ok1 ? sy[4096 + ci * 32 + iw1c] : 0.f;
        const float* wb = sw + ci * 48 + co * 16;
        accE += y00 * wb[pw]      + y01 * wb[pw + 2]
              + y10 * wb[8 + pw]  + y11 * wb[8 + pw + 2];
        accO += y00 * wb[4 + pw]  + y01 * wb[4 + pw + 2]
              + y10 * wb[12 + pw] + y11 * wb[12 + pw + 2];
    }
    float bi = bias[co];
    int base = b * (3 * 4096) + co * 4096 + (2 * t) * 64 + ow;
    out[base]      = accE + bi;
    out[base + 64] = accO + bi;
}

// ---------------- finalize: loss + perplexity ----------------
__global__ void k_final(float* __restrict__ out) {
    __shared__ double sd[1024];
    int t = threadIdx.x;
    double pr = (double)g_counts[t] / (double)NROWS;
    sd[t] = pr * log(pr + 1e-10);
    __syncthreads();
    for (int s = 512; s > 0; s >>= 1) {
        if (t < s) sd[t] += sd[t + s];
        __syncthreads();
    }
    if (t == 0) {
        out[786432] = (float)(1.25 * g_sse / NELEMF);  // loss = (1+beta)*mse
        out[786433] = (float)exp(-sd[0]);              // perplexity
    }
}

// ---------------- launch ----------------
extern "C" void kernel_launch(void* const* d_in, const int* in_sizes, int n_in,
                              void* d_out, int out_size) {
    const float* x   = (const float*)d_in[0];
    const float* ew1 = (const float*)d_in[1];
    const float* eb1 = (const float*)d_in[2];
    const float* ew2 = (const float*)d_in[3];
    const float* eb2 = (const float*)d_in[4];
    const float* cb  = (const float*)d_in[5];
    const float* dw1 = (const float*)d_in[6];
    const float* db1 = (const float*)d_in[7];
    const float* dw2 = (const float*)d_in[8];
    const float* db2 = (const float*)d_in[9];
    float* out = (float*)d_out;

    // k_vqt smem: Ah 128*136*2 = 34816, Bh 2*64*136*2 = 34816,
    //             cns 4096 + scode 512 + lred 1024  => 75264 B (2 blocks/SM)
    int vq_smem = 34816 + 34816 + 4096 + 512 + 1024;
    cudaFuncSetAttribute(k_vqt, cudaFuncAttributeMaxDynamicSharedMemorySize,
                         vq_smem);
    cudaFuncSetAttribute(k_dec2, cudaFuncAttributeMaxDynamicSharedMemorySize,
                         (8192 + 6144) * (int)sizeof(float));

    k_prep<<<512, 256>>>(cb, dw1);
    k_conv1<<<dim3(16, NB), 256>>>(x, ew1, eb1);
    k_conv2<<<dim3(15, NB), 256>>>(ew2, eb2);
    k_znorm<<<NROWS / 64, 256>>>();
    k_vqt<<<NROWS / VQ_ROWS, 256, vq_smem>>>(cb);
    k_dec1t<<<dim3(16, NB), 256>>>(db1);
    k_dec2<<<dim3(32, NB), 192, (8192 + 6144) * (int)sizeof(float)>>>(dw2, db2, out);
    k_final<<<1, 1024>>>(out);
}